// round 9
// baseline (speedup 1.0000x reference)
#include <cuda_runtime.h>
#include <cstdint>
#include <cstddef>

#define B_    2
#define N_    2048
#define DIM_  1024
#define H_    16
#define DH_   64
#define MM_   16
#define J_    2064          // N_ + MM_
#define KTOP_ 64
#define SCALE_ 0.125f

// ---------------- static device scratch ----------------
__device__ float g_q   [(size_t)B_*H_*N_*DH_];      // (b,h,i,d)
__device__ float g_k   [(size_t)B_*H_*J_*DH_];      // (b,h,j,d), j<M = mem
__device__ float g_v   [(size_t)B_*H_*J_*DH_];
__device__ float g_smix[(size_t)B_*H_*N_*J_];       // mixed scores (b,k,i,j)
__device__ float g_att [(size_t)B_*N_*DIM_];        // attention output (b,i,k*64+d)

// ---------------- tf32 MMA helpers -----------------------------------------------
__device__ __forceinline__ unsigned to_tf32(float x)
{
    unsigned r;
    asm("cvt.rna.tf32.f32 %0, %1;" : "=r"(r) : "f"(x));
    return r;
}

__device__ __forceinline__ void mma_tf32(float& d0, float& d1, float& d2, float& d3,
                                         unsigned a0, unsigned a1, unsigned a2, unsigned a3,
                                         unsigned b0, unsigned b1)
{
    asm volatile("mma.sync.aligned.m16n8k8.row.col.f32.tf32.tf32.f32 "
                 "{%0,%1,%2,%3}, {%4,%5,%6,%7}, {%8,%9}, {%0,%1,%2,%3};\n"
                 : "+f"(d0), "+f"(d1), "+f"(d2), "+f"(d3)
                 : "r"(a0), "r"(a1), "r"(a2), "r"(a3), "r"(b0), "r"(b1));
}

// ====== 128x128 / BK=16 tf32x3 tensor-MMA GEMM, reg-prefetch double buffering ====
// MODE 0: C = g_att@B + bias (A param ignored; g_att resolved in device code)
// MODE 1: scatter to g_q   (m=b*2048+i, n=h*64+d)
// MODE 2: scatter to g_k/g_v at row M+i
template<int MODE>
__global__ void __launch_bounds__(256) k_gemm(const float* __restrict__ A,
                                              const float* __restrict__ Bm,
                                              const float* __restrict__ bias,
                                              float* __restrict__ C,
                                              int Ndim, int Kdim)
{
    __shared__ unsigned Ah[128][20], Al[128][20];   // A tile [m][k], stride 20
    __shared__ unsigned Bh[16][132], Bl[16][132];   // B tile [k][n], stride 132

    const float* Aeff = (MODE == 0) ? g_att : A;    // device-side symbol resolution

    const int tid  = threadIdx.x;
    const int warp = tid >> 5;
    const int lane = tid & 31;
    const int wm   = warp & 1;
    const int wn   = warp >> 1;
    const int grp  = lane >> 2;
    const int tig  = lane & 3;
    const int m0   = blockIdx.y * 128;
    const int n0   = blockIdx.x * 128;

    const int arow = tid >> 1;
    const int acol = (tid & 1) << 3;
    const int bk   = tid >> 5;
    const int bcol = (lane) << 2;

    float acc[4][4][4];
#pragma unroll
    for (int mf = 0; mf < 4; mf++)
#pragma unroll
        for (int nf = 0; nf < 4; nf++)
#pragma unroll
            for (int e = 0; e < 4; e++) acc[mf][nf][e] = 0.f;

    const float* aptr = Aeff + (size_t)(m0 + arow) * Kdim + acol;
    const float* bptr = Bm + n0 + bcol;

    // prefetch registers (first k-slab)
    float4 ra0 = *(const float4*)(aptr);
    float4 ra1 = *(const float4*)(aptr + 4);
    float4 rb0 = *(const float4*)(bptr + (size_t)bk * Ndim);
    float4 rb1 = *(const float4*)(bptr + (size_t)(bk + 8) * Ndim);

    for (int k0 = 0; k0 < Kdim; k0 += 16) {
        // ---- split + store current slab from regs ----
        {
            const float af[8] = {ra0.x, ra0.y, ra0.z, ra0.w, ra1.x, ra1.y, ra1.z, ra1.w};
#pragma unroll
            for (int e = 0; e < 8; e++) {
                const unsigned h = to_tf32(af[e]);
                Ah[arow][acol + e] = h;
                Al[arow][acol + e] = to_tf32(af[e] - __uint_as_float(h));
            }
            const float b0f[4] = {rb0.x, rb0.y, rb0.z, rb0.w};
            const float b1f[4] = {rb1.x, rb1.y, rb1.z, rb1.w};
            unsigned hv[4], lv[4];
#pragma unroll
            for (int e = 0; e < 4; e++) {
                hv[e] = to_tf32(b0f[e]);
                lv[e] = to_tf32(b0f[e] - __uint_as_float(hv[e]));
            }
            *(uint4*)&Bh[bk][bcol] = make_uint4(hv[0], hv[1], hv[2], hv[3]);
            *(uint4*)&Bl[bk][bcol] = make_uint4(lv[0], lv[1], lv[2], lv[3]);
#pragma unroll
            for (int e = 0; e < 4; e++) {
                hv[e] = to_tf32(b1f[e]);
                lv[e] = to_tf32(b1f[e] - __uint_as_float(hv[e]));
            }
            *(uint4*)&Bh[bk + 8][bcol] = make_uint4(hv[0], hv[1], hv[2], hv[3]);
            *(uint4*)&Bl[bk + 8][bcol] = make_uint4(lv[0], lv[1], lv[2], lv[3]);
        }
        __syncthreads();

        // ---- issue next slab's loads (fly under the MMA phase) ----
        if (k0 + 16 < Kdim) {
            ra0 = *(const float4*)(aptr + k0 + 16);
            ra1 = *(const float4*)(aptr + k0 + 20);
            rb0 = *(const float4*)(bptr + (size_t)(k0 + 16 + bk) * Ndim);
            rb1 = *(const float4*)(bptr + (size_t)(k0 + 24 + bk) * Ndim);
        }

        // ---- MMA phase ----
#pragma unroll
        for (int ks = 0; ks < 2; ks++) {
            const int kk = ks * 8 + tig;
            unsigned ah[4][4], al[4][4], bh[4][2], bl[4][2];
#pragma unroll
            for (int nf = 0; nf < 4; nf++) {
                const int col = wn * 32 + nf * 8 + grp;
                bh[nf][0] = Bh[kk][col];     bh[nf][1] = Bh[kk + 4][col];
                bl[nf][0] = Bl[kk][col];     bl[nf][1] = Bl[kk + 4][col];
            }
#pragma unroll
            for (int mf = 0; mf < 4; mf++) {
                const int row = wm * 64 + mf * 16 + grp;
                ah[mf][0] = Ah[row][kk];     ah[mf][1] = Ah[row + 8][kk];
                ah[mf][2] = Ah[row][kk + 4]; ah[mf][3] = Ah[row + 8][kk + 4];
                al[mf][0] = Al[row][kk];     al[mf][1] = Al[row + 8][kk];
                al[mf][2] = Al[row][kk + 4]; al[mf][3] = Al[row + 8][kk + 4];
            }
#pragma unroll
            for (int mf = 0; mf < 4; mf++)
#pragma unroll
                for (int nf = 0; nf < 4; nf++) {
                    float* d = acc[mf][nf];
                    mma_tf32(d[0], d[1], d[2], d[3],
                             ah[mf][0], ah[mf][1], ah[mf][2], ah[mf][3],
                             bh[nf][0], bh[nf][1]);
                    mma_tf32(d[0], d[1], d[2], d[3],
                             al[mf][0], al[mf][1], al[mf][2], al[mf][3],
                             bh[nf][0], bh[nf][1]);
                    mma_tf32(d[0], d[1], d[2], d[3],
                             ah[mf][0], ah[mf][1], ah[mf][2], ah[mf][3],
                             bl[nf][0], bl[nf][1]);
                }
        }
        __syncthreads();
    }

#pragma unroll
    for (int mf = 0; mf < 4; mf++) {
        const int r0 = m0 + wm * 64 + mf * 16 + grp;
#pragma unroll
        for (int nf = 0; nf < 4; nf++) {
            const int c0 = n0 + wn * 32 + nf * 8 + tig * 2;
            const float* d = acc[mf][nf];
#pragma unroll
            for (int half = 0; half < 2; half++) {
                const int m = r0 + half * 8;
                float2 o = make_float2(d[half * 2], d[half * 2 + 1]);
                if (MODE == 0) {
                    o.x += bias[c0]; o.y += bias[c0 + 1];
                    *(float2*)(C + (size_t)m * Ndim + c0) = o;
                } else {
                    const int b = m >> 11;
                    const int i = m & (N_ - 1);
                    if (MODE == 1) {
                        const int h = c0 >> 6, dd = c0 & 63;
                        *(float2*)(g_q + (((size_t)(b * H_ + h)) * N_ + i) * DH_ + dd) = o;
                    } else {
                        if (c0 < DIM_) {
                            const int h = c0 >> 6, dd = c0 & 63;
                            *(float2*)(g_k + (((size_t)(b * H_ + h)) * J_ + MM_ + i) * DH_ + dd) = o;
                        } else {
                            const int c = c0 - DIM_;
                            const int h = c >> 6, dd = c & 63;
                            *(float2*)(g_v + (((size_t)(b * H_ + h)) * J_ + MM_ + i) * DH_ + dd) = o;
                        }
                    }
                }
            }
        }
    }
}

__global__ void k_fill_mem(const float* __restrict__ mk, const float* __restrict__ mv)
{
    int idx = blockIdx.x * blockDim.x + threadIdx.x;      // B*H*M*DH elems
    int d = idx & 63;
    int r = idx >> 6;
    int j  = r % MM_;  r /= MM_;
    int h  = r % H_;
    int b  = r / H_;
    size_t dst = (((size_t)(b * H_ + h)) * J_ + j) * DH_ + d;
    size_t src = ((size_t)h * MM_ + j) * DH_ + d;
    g_k[dst] = mk[src];
    g_v[dst] = mv[src];
}

// ---------------- fused QK^T + head-mix via tf32x3 MMA (K pre-split) -------------
// CTA tile: 32(i) x 32(j). K is split hi/lo once at load; Q split in-loop.
__global__ void __launch_bounds__(256) k_dots_mix(const float* __restrict__ pre)
{
    const int b  = blockIdx.z;
    const int i0 = blockIdx.y * 32;
    const int j0 = blockIdx.x * 32;
    if (j0 > i0 + 31 + MM_) return;     // fully above causal band

    __shared__ __align__(16) float Qs[32][68];
    __shared__ unsigned Kh[32][68], Kl[32][68];
    __shared__ float Ppre[H_ * H_];

    const int tid  = threadIdx.x;
    const int warp = tid >> 5;
    const int lane = tid & 31;
    const int wi   = warp & 1;
    const int wj   = warp >> 1;
    const int grp  = lane >> 2;
    const int tig  = lane & 3;

    Ppre[tid] = pre[tid];

    const int lr = tid >> 3;
    const int lc = (tid & 7) << 2;

    const int ri = wi * 16 + grp;
    const int rj = wj * 8 + grp;

    float acc[H_][4];
#pragma unroll
    for (int ko = 0; ko < H_; ko++)
#pragma unroll
        for (int e = 0; e < 4; e++) acc[ko][e] = 0.f;

#pragma unroll 1
    for (int h = 0; h < H_; h++) {
        const float* qrow = g_q + (((size_t)(b * H_ + h)) * N_ + i0 + lr) * DH_;
        *(float4*)&Qs[lr][lc]      = *(const float4*)(qrow + lc);
        *(float4*)&Qs[lr][lc + 32] = *(const float4*)(qrow + lc + 32);
        const int jrow = j0 + lr;
        if (jrow < J_) {
            const float* krow = g_k + (((size_t)(b * H_ + h)) * J_ + jrow) * DH_;
            const float4 k0v = *(const float4*)(krow + lc);
            const float4 k1v = *(const float4*)(krow + lc + 32);
            const float kf[8] = {k0v.x, k0v.y, k0v.z, k0v.w, k1v.x, k1v.y, k1v.z, k1v.w};
#pragma unroll
            for (int e = 0; e < 8; e++) {
                const int c = (e < 4) ? lc + e : lc + 28 + e;
                const unsigned hh = to_tf32(kf[e]);
                Kh[lr][c] = hh;
                Kl[lr][c] = to_tf32(kf[e] - __uint_as_float(hh));
            }
        } else {
#pragma unroll
            for (int e = 0; e < 8; e++) {
                const int c = (e < 4) ? lc + e : lc + 28 + e;
                Kh[lr][c] = 0u;
                Kl[lr][c] = 0u;
            }
        }
        __syncthreads();

        float s0 = 0.f, s1 = 0.f, s2 = 0.f, s3 = 0.f;
#pragma unroll
        for (int k0 = 0; k0 < DH_; k0 += 8) {
            const float a0f = Qs[ri]    [k0 + tig];
            const float a1f = Qs[ri + 8][k0 + tig];
            const float a2f = Qs[ri]    [k0 + tig + 4];
            const float a3f = Qs[ri + 8][k0 + tig + 4];
            const unsigned b0h = Kh[rj][k0 + tig], b1h = Kh[rj][k0 + tig + 4];
            const unsigned b0l = Kl[rj][k0 + tig], b1l = Kl[rj][k0 + tig + 4];

            const unsigned a0h = to_tf32(a0f), a1h = to_tf32(a1f);
            const unsigned a2h = to_tf32(a2f), a3h = to_tf32(a3f);
            const unsigned a0l = to_tf32(a0f - __uint_as_float(a0h));
            const unsigned a1l = to_tf32(a1f - __uint_as_float(a1h));
            const unsigned a2l = to_tf32(a2f - __uint_as_float(a2h));
            const unsigned a3l = to_tf32(a3f - __uint_as_float(a3h));

            mma_tf32(s0, s1, s2, s3, a0h, a1h, a2h, a3h, b0h, b1h);   // hi*hi
            mma_tf32(s0, s1, s2, s3, a0l, a1l, a2l, a3l, b0h, b1h);   // lo*hi
            mma_tf32(s0, s1, s2, s3, a0h, a1h, a2h, a3h, b0l, b1l);   // hi*lo
        }

#pragma unroll
        for (int ko = 0; ko < H_; ko++) {
            const float p = Ppre[h * H_ + ko] * SCALE_;
            acc[ko][0] += p * s0; acc[ko][1] += p * s1;
            acc[ko][2] += p * s2; acc[ko][3] += p * s3;
        }
        __syncthreads();
    }

    const int gi = i0 + ri;
    const int gj = j0 + wj * 8 + tig * 2;
#pragma unroll
    for (int ko = 0; ko < H_; ko++) {
        const size_t base = (((size_t)(b * H_ + ko)) * N_ + gi) * J_ + gj;
        if (gj < J_) {
            g_smix[base]              = acc[ko][0];
            g_smix[base + 8 * J_]     = acc[ko][2];
        }
        if (gj + 1 < J_) {
            g_smix[base + 1]          = acc[ko][1];
            g_smix[base + 8 * J_ + 1] = acc[ko][3];
        }
    }
}

// ---------------- per-row top-k + softmax + sparse A*V ---------------------------
__device__ __forceinline__ unsigned fkey(float f)
{
    unsigned u = __float_as_uint(f);
    return (u & 0x80000000u) ? ~u : (u | 0x80000000u);
}
__device__ __forceinline__ float finv(unsigned k)
{
    return (k & 0x80000000u) ? __uint_as_float(k ^ 0x80000000u)
                             : __uint_as_float(~k);
}

// single-warp suffix-scan over 256 bins; finds bin B with suffix(B) >= kth > suffix(B+1)
__device__ __forceinline__ void scan_bins(const int* hist, int kth, int tid,
                                          int* s_bin, int* s_above)
{
    if (tid < 32) {
        int loc[8];
        int sum = 0;
#pragma unroll
        for (int e = 0; e < 8; e++) { loc[e] = hist[tid * 8 + e]; sum += loc[e]; }
        int v = sum;
#pragma unroll
        for (int o = 1; o < 32; o <<= 1) {
            const int u = __shfl_down_sync(0xffffffffu, v, o);
            if (tid + o < 32) v += u;
        }
        const int after_lane = v - sum;        // count in lanes > tid
        int run = after_lane;
        int sfx[8];
#pragma unroll
        for (int e = 7; e >= 0; e--) { run += loc[e]; sfx[e] = run; }
#pragma unroll
        for (int e = 0; e < 8; e++) {
            const int above = (e == 7) ? after_lane : sfx[e + 1];
            if (sfx[e] >= kth && above < kth) { *s_bin = tid * 8 + e; *s_above = above; }
        }
    }
}

__global__ void __launch_bounds__(256) k_topk_av()
{
    const int i  = blockIdx.x;
    const int ko = blockIdx.y;
    const int b  = blockIdx.z;
    const int tid = threadIdx.x;
    const int lane = tid & 31;
    const int jmax = min(J_, i + MM_ + 1);

    __shared__ unsigned skeys[J_];
    __shared__ int   sidx[J_];       // survivor indices; reused as candB
    __shared__ float swgt[J_];       // survivor weights; reused as candA
    __shared__ int   hist[256];
    __shared__ unsigned redk[8];
    __shared__ float redf[8];
    __shared__ unsigned s_maxk, s_tkey;
    __shared__ float s_sum;
    __shared__ int   s_bin, s_above, s_cnt;
    __shared__ float accb[4][64];

    const float* row = g_smix + (((size_t)(b * H_ + ko)) * N_ + i) * J_;

    // --- load sweep fused with top-byte histogram (warp-aggregated atomics) -----
    hist[tid] = 0;
    __syncthreads();
    unsigned lmax = 0u;
    const int nIter = (jmax + 255) >> 8;
    for (int it = 0; it < nIter; it++) {
        const int j = tid + (it << 8);
        const bool valid = j < jmax;
        unsigned k = 0u;
        if (valid) {
            k = fkey(row[j]);
            skeys[j] = k;
            lmax = max(lmax, k);
        }
        const unsigned bin = valid ? (k >> 24) : 300u;     // sentinel for invalid
        const unsigned mmask = __match_any_sync(0xffffffffu, bin);
        if (valid && (mmask & ((1u << lane) - 1u)) == 0u)  // lowest lane = leader
            atomicAdd(&hist[bin], __popc(mmask));
    }
#pragma unroll
    for (int o = 16; o > 0; o >>= 1) lmax = max(lmax, __shfl_xor_sync(0xffffffffu, lmax, o));
    if (lane == 0) redk[tid >> 5] = lmax;
    __syncthreads();
    if (tid == 0) {
        unsigned m = redk[0];
#pragma unroll
        for (int w = 1; w < 8; w++) m = max(m, redk[w]);
        s_maxk = m;
    }
    __syncthreads();
    const float vmax = finv(s_maxk);

    // --- exact K-th largest key: bin scan + boundary-bin candidate select -------
    unsigned tkey = 0u;
    if (jmax > KTOP_) {
        scan_bins(hist, KTOP_, tid, &s_bin, &s_above);
        __syncthreads();
        const int b0 = s_bin;
        int kth = KTOP_ - s_above;

        if (tid == 0) s_cnt = 0;
        __syncthreads();
        unsigned* candA = (unsigned*)swgt;
        unsigned* candB = (unsigned*)sidx;
        for (int j = tid; j < jmax; j += 256) {
            const unsigned k = skeys[j];
            if ((k >> 24) == (unsigned)b0) candA[atomicAdd(&s_cnt, 1)] = k;
        }
        __syncthreads();
        int c = s_cnt;
        unsigned* cur = candA;
        unsigned* alt = candB;
        int shift = 16;
        while (c > 48 && shift >= 0) {
            hist[tid] = 0;
            __syncthreads();
            for (int t = tid; t < c; t += 256)
                atomicAdd(&hist[(cur[t] >> shift) & 255u], 1);
            __syncthreads();
            scan_bins(hist, kth, tid, &s_bin, &s_above);
            __syncthreads();
            const int bsel = s_bin;
            kth -= s_above;
            if (tid == 0) s_cnt = 0;
            __syncthreads();
            for (int t = tid; t < c; t += 256)
                if (((cur[t] >> shift) & 255u) == (unsigned)bsel)
                    alt[atomicAdd(&s_cnt, 1)] = cur[t];
            __syncthreads();
            c = s_cnt;
            unsigned* tmp = cur; cur = alt; alt = tmp;
            shift -= 8;
        }
        if (shift < 0) {
            if (tid == 0) s_tkey = cur[0];          // all remaining keys identical
        } else {
            // exact rank-count select among c (<=48) candidates
            for (int t = tid; t < c; t += 256) {
                const unsigned x = cur[t];
                int gt = 0, ge = 0;
                for (int u = 0; u < c; u++) { gt += (cur[u] > x); ge += (cur[u] >= x); }
                if (gt < kth && ge >= kth) s_tkey = x;
            }
        }
        __syncthreads();
        tkey = s_tkey;
    }

    // --- compact survivors + deterministic exp-sum ------------------------------
    if (tid == 0) s_cnt = 0;
    __syncthreads();
    float lsum = 0.f;
    for (int j = tid; j < jmax; j += 256) {
        const unsigned k = skeys[j];
        if (k >= tkey) {
            const float w = expf(finv(k) - vmax);
            lsum += w;
            const int p = atomicAdd(&s_cnt, 1);
            sidx[p] = j;
            swgt[p] = w;
        }
    }
#pragma unroll
    for (int o = 16; o > 0; o >>= 1) lsum += __shfl_xor_sync(0xffffffffu, lsum, o);
    if (lane == 0) redf[tid >> 5] = lsum;
    __syncthreads();
    if (tid == 0) {
        float t = 0.f;
#pragma unroll
        for (int w = 0; w < 8; w++) t += redf[w];
        s_sum = t;
    }
    __syncthreads();
    const float sumexp = s_sum;
    const int nsurv = s_cnt;

    // --- gather-weighted sum over surviving v rows ------------------------------
    const int d = tid & 63;
    const int g = tid >> 6;
    float acc = 0.f;
    const float* vb = g_v + ((size_t)(b * H_ + ko)) * J_ * DH_ + d;
    for (int s = g; s < nsurv; s += 4)
        acc += swgt[s] * vb[(size_t)sidx[s] * DH_];
    accb[g][d] = acc;
    __syncthreads();
    if (g == 0) {
        const float tot = accb[0][d] + accb[1][d] + accb[2][d] + accb[3][d];
        g_att[((size_t)(b * N_ + i)) * DIM_ + ko * DH_ + d] = tot / sumexp;
    }
}

// ---------------- launch ---------------------------------------------------------
extern "C" void kernel_launch(void* const* d_in, const int* in_sizes, int n_in,
                              void* d_out, int out_size)
{
    (void)in_sizes; (void)n_in; (void)out_size;
    const float* x    = (const float*)d_in[0];
    const float* Wq   = (const float*)d_in[1];
    const float* Wkv  = (const float*)d_in[2];
    const float* Wo   = (const float*)d_in[3];
    const float* bo   = (const float*)d_in[4];
    const float* pre  = (const float*)d_in[5];
    const float* memk = (const float*)d_in[7];
    const float* memv = (const float*)d_in[8];
    float* out = (float*)d_out;

    k_gemm<1><<<dim3(DIM_ / 128,     (B_ * N_) / 128), 256>>>(x, Wq, nullptr, nullptr, DIM_, DIM_);
    k_gemm<2><<<dim3(2 * DIM_ / 128, (B_ * N_) / 128), 256>>>(x, Wkv, nullptr, nullptr, 2 * DIM_, DIM_);
    k_fill_mem<<<(B_ * H_ * MM_ * DH_) / 256, 256>>>(memk, memv);
    k_dots_mix<<<dim3((J_ + 31) / 32, N_ / 32, B_), 256>>>(pre);
    k_topk_av<<<dim3(N_, H_, B_), 256>>>();
    // MODE 0 reads g_att internally (device-side symbol); A arg is a dummy.
    k_gemm<0><<<dim3(DIM_ / 128, (B_ * N_) / 128), 256>>>(nullptr, Wo, bo, out, DIM_, DIM_);
}

// round 10
// speedup vs baseline: 1.1146x; 1.1146x over previous
#include <cuda_runtime.h>
#include <cstdint>
#include <cstddef>

#define B_    2
#define N_    2048
#define DIM_  1024
#define H_    16
#define DH_   64
#define MM_   16
#define J_    2064          // N_ + MM_
#define KTOP_ 64
#define SCALE_ 0.125f

// ---------------- static device scratch ----------------
__device__ float g_q   [(size_t)B_*H_*N_*DH_];      // (b,h,i,d)
__device__ float g_k   [(size_t)B_*H_*J_*DH_];      // (b,h,j,d), j<M = mem
__device__ float g_v   [(size_t)B_*H_*J_*DH_];
__device__ float g_smix[(size_t)B_*H_*N_*J_];       // mixed scores (b,k,i,j)
__device__ float g_att [(size_t)B_*N_*DIM_];        // attention output (b,i,k*64+d)

// ---------------- tf32 MMA helpers -----------------------------------------------
__device__ __forceinline__ unsigned to_tf32(float x)
{
    unsigned r;
    asm("cvt.rna.tf32.f32 %0, %1;" : "=r"(r) : "f"(x));
    return r;
}

__device__ __forceinline__ void mma_tf32(float& d0, float& d1, float& d2, float& d3,
                                         unsigned a0, unsigned a1, unsigned a2, unsigned a3,
                                         unsigned b0, unsigned b1)
{
    asm volatile("mma.sync.aligned.m16n8k8.row.col.f32.tf32.tf32.f32 "
                 "{%0,%1,%2,%3}, {%4,%5,%6,%7}, {%8,%9}, {%0,%1,%2,%3};\n"
                 : "+f"(d0), "+f"(d1), "+f"(d2), "+f"(d3)
                 : "r"(a0), "r"(a1), "r"(a2), "r"(a3), "r"(b0), "r"(b1));
}

// =============== shared GEMM inner body (round-8 form, no reg prefetch) ==========
// Computes the 128x128 tile product into acc[4][4][4] given A base ptr and B tile
// addressing. Ah/Al/Bh/Bl are the caller's shared buffers.
struct GemmSmem {
    unsigned Ah[128][20], Al[128][20];
    unsigned Bh[16][132], Bl[16][132];
};

__device__ __forceinline__ void gemm_tiles(GemmSmem& S,
                                           const float* __restrict__ Aeff,
                                           const float* __restrict__ Bm,
                                           int Ndim, int Kdim,
                                           int m0, int n0,
                                           float acc[4][4][4])
{
    const int tid  = threadIdx.x;
    const int warp = tid >> 5;
    const int lane = tid & 31;
    const int wm   = warp & 1;
    const int wn   = warp >> 1;
    const int grp  = lane >> 2;
    const int tig  = lane & 3;

    const int arow = tid >> 1;
    const int acol = (tid & 1) << 3;
    const int bk   = tid >> 5;
    const int bcol = (lane) << 2;

    const float* aptr = Aeff + (size_t)(m0 + arow) * Kdim + acol;

    for (int k0 = 0; k0 < Kdim; k0 += 16) {
        {
            const float4 a0 = *(const float4*)(aptr + k0);
            const float4 a1 = *(const float4*)(aptr + k0 + 4);
            const float af[8] = {a0.x, a0.y, a0.z, a0.w, a1.x, a1.y, a1.z, a1.w};
#pragma unroll
            for (int e = 0; e < 8; e++) {
                const unsigned h = to_tf32(af[e]);
                S.Ah[arow][acol + e] = h;
                S.Al[arow][acol + e] = to_tf32(af[e] - __uint_as_float(h));
            }
        }
#pragma unroll
        for (int t = 0; t < 2; t++) {
            const int kr = bk + t * 8;
            const float4 bv = *(const float4*)(Bm + (size_t)(k0 + kr) * Ndim + n0 + bcol);
            const float bf[4] = {bv.x, bv.y, bv.z, bv.w};
            unsigned hv[4], lv[4];
#pragma unroll
            for (int e = 0; e < 4; e++) {
                hv[e] = to_tf32(bf[e]);
                lv[e] = to_tf32(bf[e] - __uint_as_float(hv[e]));
            }
            *(uint4*)&S.Bh[kr][bcol] = make_uint4(hv[0], hv[1], hv[2], hv[3]);
            *(uint4*)&S.Bl[kr][bcol] = make_uint4(lv[0], lv[1], lv[2], lv[3]);
        }
        __syncthreads();

#pragma unroll
        for (int ks = 0; ks < 2; ks++) {
            const int kk = ks * 8 + tig;
            unsigned ah[4][4], al[4][4], bh[4][2], bl[4][2];
#pragma unroll
            for (int nf = 0; nf < 4; nf++) {
                const int col = wn * 32 + nf * 8 + grp;
                bh[nf][0] = S.Bh[kk][col];     bh[nf][1] = S.Bh[kk + 4][col];
                bl[nf][0] = S.Bl[kk][col];     bl[nf][1] = S.Bl[kk + 4][col];
            }
#pragma unroll
            for (int mf = 0; mf < 4; mf++) {
                const int row = wm * 64 + mf * 16 + grp;
                ah[mf][0] = S.Ah[row][kk];     ah[mf][1] = S.Ah[row + 8][kk];
                ah[mf][2] = S.Ah[row][kk + 4]; ah[mf][3] = S.Ah[row + 8][kk + 4];
                al[mf][0] = S.Al[row][kk];     al[mf][1] = S.Al[row + 8][kk];
                al[mf][2] = S.Al[row][kk + 4]; al[mf][3] = S.Al[row + 8][kk + 4];
            }
#pragma unroll
            for (int mf = 0; mf < 4; mf++)
#pragma unroll
                for (int nf = 0; nf < 4; nf++) {
                    float* d = acc[mf][nf];
                    mma_tf32(d[0], d[1], d[2], d[3],
                             ah[mf][0], ah[mf][1], ah[mf][2], ah[mf][3],
                             bh[nf][0], bh[nf][1]);
                    mma_tf32(d[0], d[1], d[2], d[3],
                             al[mf][0], al[mf][1], al[mf][2], al[mf][3],
                             bh[nf][0], bh[nf][1]);
                    mma_tf32(d[0], d[1], d[2], d[3],
                             ah[mf][0], ah[mf][1], ah[mf][2], ah[mf][3],
                             bl[nf][0], bl[nf][1]);
                }
        }
        __syncthreads();
    }
}

// ---- merged Q/KV projection: grid.x = 24 tiles over [Wq | Wkv] columns ----------
__global__ void __launch_bounds__(256) k_gemm_qkv(const float* __restrict__ x,
                                                  const float* __restrict__ Wq,
                                                  const float* __restrict__ Wkv)
{
    __shared__ GemmSmem S;

    const int n0g = blockIdx.x * 128;        // 0..3071
    const int m0  = blockIdx.y * 128;
    const bool isQ = n0g < DIM_;
    const float* Bm = isQ ? Wq : Wkv;
    const int Ndim  = isQ ? DIM_ : 2 * DIM_;
    const int n0    = isQ ? n0g : n0g - DIM_;

    float acc[4][4][4];
#pragma unroll
    for (int mf = 0; mf < 4; mf++)
#pragma unroll
        for (int nf = 0; nf < 4; nf++)
#pragma unroll
            for (int e = 0; e < 4; e++) acc[mf][nf][e] = 0.f;

    gemm_tiles(S, x, Bm, Ndim, DIM_, m0, n0, acc);

    const int tid  = threadIdx.x;
    const int warp = tid >> 5;
    const int lane = tid & 31;
    const int wm   = warp & 1;
    const int wn   = warp >> 1;
    const int grp  = lane >> 2;
    const int tig  = lane & 3;

#pragma unroll
    for (int mf = 0; mf < 4; mf++) {
        const int r0 = m0 + wm * 64 + mf * 16 + grp;
#pragma unroll
        for (int nf = 0; nf < 4; nf++) {
            const int c0 = n0 + wn * 32 + nf * 8 + tig * 2;
            const float* d = acc[mf][nf];
#pragma unroll
            for (int half = 0; half < 2; half++) {
                const int m = r0 + half * 8;
                const float2 o = make_float2(d[half * 2], d[half * 2 + 1]);
                const int b = m >> 11;
                const int i = m & (N_ - 1);
                if (isQ) {
                    const int h = c0 >> 6, dd = c0 & 63;
                    *(float2*)(g_q + (((size_t)(b * H_ + h)) * N_ + i) * DH_ + dd) = o;
                } else if (c0 < DIM_) {
                    const int h = c0 >> 6, dd = c0 & 63;
                    *(float2*)(g_k + (((size_t)(b * H_ + h)) * J_ + MM_ + i) * DH_ + dd) = o;
                } else {
                    const int c = c0 - DIM_;
                    const int h = c >> 6, dd = c & 63;
                    *(float2*)(g_v + (((size_t)(b * H_ + h)) * J_ + MM_ + i) * DH_ + dd) = o;
                }
            }
        }
    }
}

// ---- output projection: C = g_att @ Wo + bo -------------------------------------
__global__ void __launch_bounds__(256) k_gemm_o(const float* __restrict__ Wo,
                                                const float* __restrict__ bias,
                                                float* __restrict__ C)
{
    __shared__ GemmSmem S;

    const int m0 = blockIdx.y * 128;
    const int n0 = blockIdx.x * 128;

    float acc[4][4][4];
#pragma unroll
    for (int mf = 0; mf < 4; mf++)
#pragma unroll
        for (int nf = 0; nf < 4; nf++)
#pragma unroll
            for (int e = 0; e < 4; e++) acc[mf][nf][e] = 0.f;

    gemm_tiles(S, g_att, Wo, DIM_, DIM_, m0, n0, acc);

    const int tid  = threadIdx.x;
    const int warp = tid >> 5;
    const int lane = tid & 31;
    const int wm   = warp & 1;
    const int wn   = warp >> 1;
    const int grp  = lane >> 2;
    const int tig  = lane & 3;

#pragma unroll
    for (int mf = 0; mf < 4; mf++) {
        const int r0 = m0 + wm * 64 + mf * 16 + grp;
#pragma unroll
        for (int nf = 0; nf < 4; nf++) {
            const int c0 = n0 + wn * 32 + nf * 8 + tig * 2;
            const float* d = acc[mf][nf];
#pragma unroll
            for (int half = 0; half < 2; half++) {
                const int m = r0 + half * 8;
                float2 o = make_float2(d[half * 2], d[half * 2 + 1]);
                o.x += bias[c0]; o.y += bias[c0 + 1];
                *(float2*)(C + (size_t)m * DIM_ + c0) = o;
            }
        }
    }
}

__global__ void k_fill_mem(const float* __restrict__ mk, const float* __restrict__ mv)
{
    int idx = blockIdx.x * blockDim.x + threadIdx.x;      // B*H*M*DH elems
    int d = idx & 63;
    int r = idx >> 6;
    int j  = r % MM_;  r /= MM_;
    int h  = r % H_;
    int b  = r / H_;
    size_t dst = (((size_t)(b * H_ + h)) * J_ + j) * DH_ + d;
    size_t src = ((size_t)h * MM_ + j) * DH_ + d;
    g_k[dst] = mk[src];
    g_v[dst] = mv[src];
}

// ---------------- fused QK^T + head-mix via tf32x3 MMA, double-buffered ----------
// CTA tile: 32(i) x 32(j); 8 warps, each a 16x8 sub-tile. Tiles for head h+1 are
// LDG-staged in registers during head h's MMA phase; ONE barrier per head.
__global__ void __launch_bounds__(256, 2) k_dots_mix(const float* __restrict__ pre)
{
    const int b  = blockIdx.z;
    const int i0 = blockIdx.y * 32;
    const int j0 = blockIdx.x * 32;
    if (j0 > i0 + 31 + MM_) return;     // fully above causal band

    __shared__ __align__(16) float Qs[2][32][68];
    __shared__ __align__(16) float Ks[2][32][68];
    __shared__ float Ppre[H_ * H_];

    const int tid  = threadIdx.x;
    const int warp = tid >> 5;
    const int lane = tid & 31;
    const int wi   = warp & 1;
    const int wj   = warp >> 1;
    const int grp  = lane >> 2;
    const int tig  = lane & 3;

    Ppre[tid] = pre[tid];

    const int lr = tid >> 3;
    const int lc = (tid & 7) << 2;
    const int jrow = j0 + lr;
    const bool jvalid = jrow < J_;

    const int ri = wi * 16 + grp;
    const int rj = wj * 8 + grp;

    float acc[H_][4];
#pragma unroll
    for (int ko = 0; ko < H_; ko++)
#pragma unroll
        for (int e = 0; e < 4; e++) acc[ko][e] = 0.f;

    const float* qbase = g_q + ((size_t)b * H_ * N_ + (size_t)(i0 + lr)) * DH_;
    const float* kbase = g_k + ((size_t)b * H_ * J_ + (size_t)jrow) * DH_;
    const size_t qstep = (size_t)N_ * DH_;      // per-head stride
    const size_t kstep = (size_t)J_ * DH_;

    // prologue: load head 0 into regs, store to buffer 0
    float4 q0r = *(const float4*)(qbase + lc);
    float4 q1r = *(const float4*)(qbase + lc + 32);
    float4 k0r, k1r;
    if (jvalid) {
        k0r = *(const float4*)(kbase + lc);
        k1r = *(const float4*)(kbase + lc + 32);
    } else {
        k0r = make_float4(0.f, 0.f, 0.f, 0.f);
        k1r = k0r;
    }
    *(float4*)&Qs[0][lr][lc]      = q0r;
    *(float4*)&Qs[0][lr][lc + 32] = q1r;
    *(float4*)&Ks[0][lr][lc]      = k0r;
    *(float4*)&Ks[0][lr][lc + 32] = k1r;

#pragma unroll 1
    for (int h = 0; h < H_; h++) {
        const int cb = h & 1;
        // stage next head's tiles into registers (LDG flies under the MMA phase)
        if (h + 1 < H_) {
            const float* qn = qbase + (size_t)(h + 1) * qstep;
            q0r = *(const float4*)(qn + lc);
            q1r = *(const float4*)(qn + lc + 32);
            if (jvalid) {
                const float* kn = kbase + (size_t)(h + 1) * kstep;
                k0r = *(const float4*)(kn + lc);
                k1r = *(const float4*)(kn + lc + 32);
            }
        }
        __syncthreads();                 // buffer cb stores (prev iter) visible

        float s0 = 0.f, s1 = 0.f, s2 = 0.f, s3 = 0.f;
#pragma unroll
        for (int k0 = 0; k0 < DH_; k0 += 8) {
            const float a0f = Qs[cb][ri]    [k0 + tig];
            const float a1f = Qs[cb][ri + 8][k0 + tig];
            const float a2f = Qs[cb][ri]    [k0 + tig + 4];
            const float a3f = Qs[cb][ri + 8][k0 + tig + 4];
            const float b0f = Ks[cb][rj][k0 + tig];
            const float b1f = Ks[cb][rj][k0 + tig + 4];

            const unsigned a0h = to_tf32(a0f), a1h = to_tf32(a1f);
            const unsigned a2h = to_tf32(a2f), a3h = to_tf32(a3f);
            const unsigned b0h = to_tf32(b0f), b1h = to_tf32(b1f);
            const unsigned a0l = to_tf32(a0f - __uint_as_float(a0h));
            const unsigned a1l = to_tf32(a1f - __uint_as_float(a1h));
            const unsigned a2l = to_tf32(a2f - __uint_as_float(a2h));
            const unsigned a3l = to_tf32(a3f - __uint_as_float(a3h));
            const unsigned b0l = to_tf32(b0f - __uint_as_float(b0h));
            const unsigned b1l = to_tf32(b1f - __uint_as_float(b1h));

            mma_tf32(s0, s1, s2, s3, a0h, a1h, a2h, a3h, b0h, b1h);   // hi*hi
            mma_tf32(s0, s1, s2, s3, a0l, a1l, a2l, a3l, b0h, b1h);   // lo*hi
            mma_tf32(s0, s1, s2, s3, a0h, a1h, a2h, a3h, b0l, b1l);   // hi*lo
        }

#pragma unroll
        for (int ko = 0; ko < H_; ko++) {
            const float p = Ppre[h * H_ + ko] * SCALE_;
            acc[ko][0] += p * s0; acc[ko][1] += p * s1;
            acc[ko][2] += p * s2; acc[ko][3] += p * s3;
        }

        // store next head's tiles into the other buffer (reads of it finished
        // before the barrier above)
        if (h + 1 < H_) {
            const int nb = cb ^ 1;
            *(float4*)&Qs[nb][lr][lc]      = q0r;
            *(float4*)&Qs[nb][lr][lc + 32] = q1r;
            *(float4*)&Ks[nb][lr][lc]      = k0r;
            *(float4*)&Ks[nb][lr][lc + 32] = k1r;
        }
    }

    const int gi = i0 + ri;
    const int gj = j0 + wj * 8 + tig * 2;
#pragma unroll
    for (int ko = 0; ko < H_; ko++) {
        const size_t base = (((size_t)(b * H_ + ko)) * N_ + gi) * J_ + gj;
        if (gj < J_) {
            g_smix[base]              = acc[ko][0];
            g_smix[base + 8 * J_]     = acc[ko][2];
        }
        if (gj + 1 < J_) {
            g_smix[base + 1]          = acc[ko][1];
            g_smix[base + 8 * J_ + 1] = acc[ko][3];
        }
    }
}

// ---------------- per-row top-k + softmax + sparse A*V ---------------------------
__device__ __forceinline__ unsigned fkey(float f)
{
    unsigned u = __float_as_uint(f);
    return (u & 0x80000000u) ? ~u : (u | 0x80000000u);
}
__device__ __forceinline__ float finv(unsigned k)
{
    return (k & 0x80000000u) ? __uint_as_float(k ^ 0x80000000u)
                             : __uint_as_float(~k);
}

// single-warp suffix-scan over 256 bins; finds bin B with suffix(B) >= kth > suffix(B+1)
__device__ __forceinline__ void scan_bins(const int* hist, int kth, int tid,
                                          int* s_bin, int* s_above)
{
    if (tid < 32) {
        int loc[8];
        int sum = 0;
#pragma unroll
        for (int e = 0; e < 8; e++) { loc[e] = hist[tid * 8 + e]; sum += loc[e]; }
        int v = sum;
#pragma unroll
        for (int o = 1; o < 32; o <<= 1) {
            const int u = __shfl_down_sync(0xffffffffu, v, o);
            if (tid + o < 32) v += u;
        }
        const int after_lane = v - sum;        // count in lanes > tid
        int run = after_lane;
        int sfx[8];
#pragma unroll
        for (int e = 7; e >= 0; e--) { run += loc[e]; sfx[e] = run; }
#pragma unroll
        for (int e = 0; e < 8; e++) {
            const int above = (e == 7) ? after_lane : sfx[e + 1];
            if (sfx[e] >= kth && above < kth) { *s_bin = tid * 8 + e; *s_above = above; }
        }
    }
}

__global__ void __launch_bounds__(256) k_topk_av()
{
    const int i  = blockIdx.x;
    const int ko = blockIdx.y;
    const int b  = blockIdx.z;
    const int tid = threadIdx.x;
    const int lane = tid & 31;
    const int jmax = min(J_, i + MM_ + 1);

    __shared__ unsigned skeys[J_];
    __shared__ int   sidx[J_];       // survivor indices; reused as candB
    __shared__ float swgt[J_];       // survivor weights; reused as candA
    __shared__ int   hist[256];
    __shared__ unsigned redk[8];
    __shared__ float redf[8];
    __shared__ unsigned s_maxk, s_tkey;
    __shared__ float s_sum;
    __shared__ int   s_bin, s_above, s_cnt;
    __shared__ float accb[4][64];

    const float* row = g_smix + (((size_t)(b * H_ + ko)) * N_ + i) * J_;

    // --- load sweep fused with top-byte histogram (warp-aggregated atomics) -----
    hist[tid] = 0;
    __syncthreads();
    unsigned lmax = 0u;
    const int nIter = (jmax + 255) >> 8;
    for (int it = 0; it < nIter; it++) {
        const int j = tid + (it << 8);
        const bool valid = j < jmax;
        unsigned k = 0u;
        if (valid) {
            k = fkey(row[j]);
            skeys[j] = k;
            lmax = max(lmax, k);
        }
        const unsigned bin = valid ? (k >> 24) : 300u;     // sentinel for invalid
        const unsigned mmask = __match_any_sync(0xffffffffu, bin);
        if (valid && (mmask & ((1u << lane) - 1u)) == 0u)  // lowest lane = leader
            atomicAdd(&hist[bin], __popc(mmask));
    }
#pragma unroll
    for (int o = 16; o > 0; o >>= 1) lmax = max(lmax, __shfl_xor_sync(0xffffffffu, lmax, o));
    if (lane == 0) redk[tid >> 5] = lmax;
    __syncthreads();
    if (tid == 0) {
        unsigned m = redk[0];
#pragma unroll
        for (int w = 1; w < 8; w++) m = max(m, redk[w]);
        s_maxk = m;
    }
    __syncthreads();
    const float vmax = finv(s_maxk);

    // --- exact K-th largest key: bin scan + boundary-bin candidate select -------
    unsigned tkey = 0u;
    if (jmax > KTOP_) {
        scan_bins(hist, KTOP_, tid, &s_bin, &s_above);
        __syncthreads();
        const int b0 = s_bin;
        int kth = KTOP_ - s_above;

        if (tid == 0) s_cnt = 0;
        __syncthreads();
        unsigned* candA = (unsigned*)swgt;
        unsigned* candB = (unsigned*)sidx;
        for (int j = tid; j < jmax; j += 256) {
            const unsigned k = skeys[j];
            if ((k >> 24) == (unsigned)b0) candA[atomicAdd(&s_cnt, 1)] = k;
        }
        __syncthreads();
        int c = s_cnt;
        unsigned* cur = candA;
        unsigned* alt = candB;
        int shift = 16;
        while (c > 48 && shift >= 0) {
            hist[tid] = 0;
            __syncthreads();
            for (int t = tid; t < c; t += 256)
                atomicAdd(&hist[(cur[t] >> shift) & 255u], 1);
            __syncthreads();
            scan_bins(hist, kth, tid, &s_bin, &s_above);
            __syncthreads();
            const int bsel = s_bin;
            kth -= s_above;
            if (tid == 0) s_cnt = 0;
            __syncthreads();
            for (int t = tid; t < c; t += 256)
                if (((cur[t] >> shift) & 255u) == (unsigned)bsel)
                    alt[atomicAdd(&s_cnt, 1)] = cur[t];
            __syncthreads();
            c = s_cnt;
            unsigned* tmp = cur; cur = alt; alt = tmp;
            shift -= 8;
        }
        if (shift < 0) {
            if (tid == 0) s_tkey = cur[0];          // all remaining keys identical
        } else {
            // exact rank-count select among c (<=48) candidates
            for (int t = tid; t < c; t += 256) {
                const unsigned x = cur[t];
                int gt = 0, ge = 0;
                for (int u = 0; u < c; u++) { gt += (cur[u] > x); ge += (cur[u] >= x); }
                if (gt < kth && ge >= kth) s_tkey = x;
            }
        }
        __syncthreads();
        tkey = s_tkey;
    }

    // --- compact survivors + deterministic exp-sum ------------------------------
    if (tid == 0) s_cnt = 0;
    __syncthreads();
    float lsum = 0.f;
    for (int j = tid; j < jmax; j += 256) {
        const unsigned k = skeys[j];
        if (k >= tkey) {
            const float w = expf(finv(k) - vmax);
            lsum += w;
            const int p = atomicAdd(&s_cnt, 1);
            sidx[p] = j;
            swgt[p] = w;
        }
    }
#pragma unroll
    for (int o = 16; o > 0; o >>= 1) lsum += __shfl_xor_sync(0xffffffffu, lsum, o);
    if (lane == 0) redf[tid >> 5] = lsum;
    __syncthreads();
    if (tid == 0) {
        float t = 0.f;
#pragma unroll
        for (int w = 0; w < 8; w++) t += redf[w];
        s_sum = t;
    }
    __syncthreads();
    const float sumexp = s_sum;
    const int nsurv = s_cnt;

    // --- gather-weighted sum over surviving v rows ------------------------------
    const int d = tid & 63;
    const int g = tid >> 6;
    float acc = 0.f;
    const float* vb = g_v + ((size_t)(b * H_ + ko)) * J_ * DH_ + d;
    for (int s = g; s < nsurv; s += 4)
        acc += swgt[s] * vb[(size_t)sidx[s] * DH_];
    accb[g][d] = acc;
    __syncthreads();
    if (g == 0) {
        const float tot = accb[0][d] + accb[1][d] + accb[2][d] + accb[3][d];
        g_att[((size_t)(b * N_ + i)) * DIM_ + ko * DH_ + d] = tot / sumexp;
    }
}

// ---------------- launch ---------------------------------------------------------
extern "C" void kernel_launch(void* const* d_in, const int* in_sizes, int n_in,
                              void* d_out, int out_size)
{
    (void)in_sizes; (void)n_in; (void)out_size;
    const float* x    = (const float*)d_in[0];
    const float* Wq   = (const float*)d_in[1];
    const float* Wkv  = (const float*)d_in[2];
    const float* Wo   = (const float*)d_in[3];
    const float* bo   = (const float*)d_in[4];
    const float* pre  = (const float*)d_in[5];
    const float* memk = (const float*)d_in[7];
    const float* memv = (const float*)d_in[8];
    float* out = (float*)d_out;

    k_gemm_qkv<<<dim3(3 * DIM_ / 128, (B_ * N_) / 128), 256>>>(x, Wq, Wkv);
    k_fill_mem<<<(B_ * H_ * MM_ * DH_) / 256, 256>>>(memk, memv);
    k_dots_mix<<<dim3((J_ + 31) / 32, N_ / 32, B_), 256>>>(pre);
    k_topk_av<<<dim3(N_, H_, B_), 256>>>();
    k_gemm_o<<<dim3(DIM_ / 128, (B_ * N_) / 128), 256>>>(Wo, bo, out);
}

// round 11
// speedup vs baseline: 1.1146x; 1.0000x over previous
#include <cuda_runtime.h>
#include <cstdint>
#include <cstddef>

#define B_    2
#define N_    2048
#define DIM_  1024
#define H_    16
#define DH_   64
#define MM_   16
#define J_    2064          // N_ + MM_
#define KTOP_ 64
#define SCALE_ 0.125f

// ---------------- static device scratch ----------------
__device__ float g_q   [(size_t)B_*H_*N_*DH_];      // (b,h,i,d)
__device__ float g_k   [(size_t)B_*H_*J_*DH_];      // (b,h,j,d), j<M = mem
__device__ float g_v   [(size_t)B_*H_*J_*DH_];
__device__ float g_smix[(size_t)B_*H_*N_*J_];       // mixed scores (b,k,i,j)
__device__ float g_att [(size_t)B_*N_*DIM_];        // attention output (b,i,k*64+d)

// ---------------- tf32 MMA helpers -----------------------------------------------
__device__ __forceinline__ unsigned to_tf32(float x)
{
    unsigned r;
    asm("cvt.rna.tf32.f32 %0, %1;" : "=r"(r) : "f"(x));
    return r;
}

__device__ __forceinline__ void mma_tf32(float& d0, float& d1, float& d2, float& d3,
                                         unsigned a0, unsigned a1, unsigned a2, unsigned a3,
                                         unsigned b0, unsigned b1)
{
    asm volatile("mma.sync.aligned.m16n8k8.row.col.f32.tf32.tf32.f32 "
                 "{%0,%1,%2,%3}, {%4,%5,%6,%7}, {%8,%9}, {%0,%1,%2,%3};\n"
                 : "+f"(d0), "+f"(d1), "+f"(d2), "+f"(d3)
                 : "r"(a0), "r"(a1), "r"(a2), "r"(a3), "r"(b0), "r"(b1));
}

__device__ __forceinline__ unsigned smem_u32(const void* p)
{
    return (unsigned)__cvta_generic_to_shared(p);
}
#define CP16(dst, src) asm volatile("cp.async.cg.shared.global [%0], [%1], 16;" :: "r"(dst), "l"(src))
#define CP_COMMIT()    asm volatile("cp.async.commit_group;")
#define CP_WAIT1()     asm volatile("cp.async.wait_group 1;")

// ======= 128x128 / BK=16 tf32x3 GEMM, 2-stage cp.async smem pipeline =============
struct GemmSmem {
    float As[2][128][20];   // [stage][m][k]  banks: 20*grp+tig -> conflict-free
    float Bs[2][16][136];   // [stage][k][n]  banks: 8*tig+grp  -> conflict-free
};

__device__ __forceinline__ void gemm_tiles(GemmSmem& S,
                                           const float* __restrict__ Aeff,
                                           const float* __restrict__ Bm,
                                           int Ndim, int Kdim,
                                           int m0, int n0,
                                           float acc[4][4][4])
{
    const int tid  = threadIdx.x;
    const int warp = tid >> 5;
    const int lane = tid & 31;
    const int wm   = warp & 1;
    const int wn   = warp >> 1;
    const int grp  = lane >> 2;
    const int tig  = lane & 3;

    const int arow  = tid >> 1;          // 0..127
    const int acol8 = (tid & 1) * 8;     // 0 or 8
    const int brow  = tid >> 4;          // 0..15
    const int bcol8 = (tid & 15) * 8;    // 0..120

    const float* ag = Aeff + (size_t)(m0 + arow) * Kdim + acol8;
    const float* bg = Bm + n0 + bcol8;

    unsigned a_dst[2], b_dst[2];
    a_dst[0] = smem_u32(&S.As[0][arow][acol8]);
    a_dst[1] = smem_u32(&S.As[1][arow][acol8]);
    b_dst[0] = smem_u32(&S.Bs[0][brow][bcol8]);
    b_dst[1] = smem_u32(&S.Bs[1][brow][bcol8]);

    // prologue: stage 0
    CP16(a_dst[0],      ag);
    CP16(a_dst[0] + 16, ag + 4);
    CP16(b_dst[0],      bg + (size_t)brow * Ndim);
    CP16(b_dst[0] + 16, bg + (size_t)brow * Ndim + 4);
    CP_COMMIT();

    int s = 0;
    for (int k0 = 0; k0 < Kdim; k0 += 16, s ^= 1) {
        if (k0 + 16 < Kdim) {
            const int ns = s ^ 1;
            CP16(a_dst[ns],      ag + k0 + 16);
            CP16(a_dst[ns] + 16, ag + k0 + 20);
            CP16(b_dst[ns],      bg + (size_t)(k0 + 16 + brow) * Ndim);
            CP16(b_dst[ns] + 16, bg + (size_t)(k0 + 16 + brow) * Ndim + 4);
        }
        CP_COMMIT();
        CP_WAIT1();
        __syncthreads();

#pragma unroll
        for (int ks = 0; ks < 2; ks++) {
            const int kk = ks * 8 + tig;
            unsigned ah[4][4], al[4][4], bh[4][2], bl[4][2];
#pragma unroll
            for (int nf = 0; nf < 4; nf++) {
                const int col = wn * 32 + nf * 8 + grp;
                const float b0f = S.Bs[s][kk][col];
                const float b1f = S.Bs[s][kk + 4][col];
                bh[nf][0] = to_tf32(b0f);
                bh[nf][1] = to_tf32(b1f);
                bl[nf][0] = to_tf32(b0f - __uint_as_float(bh[nf][0]));
                bl[nf][1] = to_tf32(b1f - __uint_as_float(bh[nf][1]));
            }
#pragma unroll
            for (int mf = 0; mf < 4; mf++) {
                const int row = wm * 64 + mf * 16 + grp;
                const float a0f = S.As[s][row][kk];
                const float a1f = S.As[s][row + 8][kk];
                const float a2f = S.As[s][row][kk + 4];
                const float a3f = S.As[s][row + 8][kk + 4];
                ah[mf][0] = to_tf32(a0f); ah[mf][1] = to_tf32(a1f);
                ah[mf][2] = to_tf32(a2f); ah[mf][3] = to_tf32(a3f);
                al[mf][0] = to_tf32(a0f - __uint_as_float(ah[mf][0]));
                al[mf][1] = to_tf32(a1f - __uint_as_float(ah[mf][1]));
                al[mf][2] = to_tf32(a2f - __uint_as_float(ah[mf][2]));
                al[mf][3] = to_tf32(a3f - __uint_as_float(ah[mf][3]));
            }
#pragma unroll
            for (int mf = 0; mf < 4; mf++)
#pragma unroll
                for (int nf = 0; nf < 4; nf++) {
                    float* d = acc[mf][nf];
                    mma_tf32(d[0], d[1], d[2], d[3],
                             ah[mf][0], ah[mf][1], ah[mf][2], ah[mf][3],
                             bh[nf][0], bh[nf][1]);
                    mma_tf32(d[0], d[1], d[2], d[3],
                             al[mf][0], al[mf][1], al[mf][2], al[mf][3],
                             bh[nf][0], bh[nf][1]);
                    mma_tf32(d[0], d[1], d[2], d[3],
                             ah[mf][0], ah[mf][1], ah[mf][2], ah[mf][3],
                             bl[nf][0], bl[nf][1]);
                }
        }
        __syncthreads();
    }
}

// ---- merged Q/KV projection: grid.x = 24 tiles over [Wq | Wkv] columns ----------
__global__ void __launch_bounds__(256) k_gemm_qkv(const float* __restrict__ x,
                                                  const float* __restrict__ Wq,
                                                  const float* __restrict__ Wkv)
{
    __shared__ GemmSmem S;

    const int n0g = blockIdx.x * 128;        // 0..3071
    const int m0  = blockIdx.y * 128;
    const bool isQ = n0g < DIM_;
    const float* Bm = isQ ? Wq : Wkv;
    const int Ndim  = isQ ? DIM_ : 2 * DIM_;
    const int n0    = isQ ? n0g : n0g - DIM_;

    float acc[4][4][4];
#pragma unroll
    for (int mf = 0; mf < 4; mf++)
#pragma unroll
        for (int nf = 0; nf < 4; nf++)
#pragma unroll
            for (int e = 0; e < 4; e++) acc[mf][nf][e] = 0.f;

    gemm_tiles(S, x, Bm, Ndim, DIM_, m0, n0, acc);

    const int tid  = threadIdx.x;
    const int warp = tid >> 5;
    const int lane = tid & 31;
    const int wm   = warp & 1;
    const int wn   = warp >> 1;
    const int grp  = lane >> 2;
    const int tig  = lane & 3;

#pragma unroll
    for (int mf = 0; mf < 4; mf++) {
        const int r0 = m0 + wm * 64 + mf * 16 + grp;
#pragma unroll
        for (int nf = 0; nf < 4; nf++) {
            const int c0 = n0 + wn * 32 + nf * 8 + tig * 2;
            const float* d = acc[mf][nf];
#pragma unroll
            for (int half = 0; half < 2; half++) {
                const int m = r0 + half * 8;
                const float2 o = make_float2(d[half * 2], d[half * 2 + 1]);
                const int b = m >> 11;
                const int i = m & (N_ - 1);
                if (isQ) {
                    const int h = c0 >> 6, dd = c0 & 63;
                    *(float2*)(g_q + (((size_t)(b * H_ + h)) * N_ + i) * DH_ + dd) = o;
                } else if (c0 < DIM_) {
                    const int h = c0 >> 6, dd = c0 & 63;
                    *(float2*)(g_k + (((size_t)(b * H_ + h)) * J_ + MM_ + i) * DH_ + dd) = o;
                } else {
                    const int c = c0 - DIM_;
                    const int h = c >> 6, dd = c & 63;
                    *(float2*)(g_v + (((size_t)(b * H_ + h)) * J_ + MM_ + i) * DH_ + dd) = o;
                }
            }
        }
    }
}

// ---- output projection: C = g_att @ Wo + bo -------------------------------------
__global__ void __launch_bounds__(256) k_gemm_o(const float* __restrict__ Wo,
                                                const float* __restrict__ bias,
                                                float* __restrict__ C)
{
    __shared__ GemmSmem S;

    const int m0 = blockIdx.y * 128;
    const int n0 = blockIdx.x * 128;

    float acc[4][4][4];
#pragma unroll
    for (int mf = 0; mf < 4; mf++)
#pragma unroll
        for (int nf = 0; nf < 4; nf++)
#pragma unroll
            for (int e = 0; e < 4; e++) acc[mf][nf][e] = 0.f;

    gemm_tiles(S, g_att, Wo, DIM_, DIM_, m0, n0, acc);

    const int tid  = threadIdx.x;
    const int warp = tid >> 5;
    const int lane = tid & 31;
    const int wm   = warp & 1;
    const int wn   = warp >> 1;
    const int grp  = lane >> 2;
    const int tig  = lane & 3;

#pragma unroll
    for (int mf = 0; mf < 4; mf++) {
        const int r0 = m0 + wm * 64 + mf * 16 + grp;
#pragma unroll
        for (int nf = 0; nf < 4; nf++) {
            const int c0 = n0 + wn * 32 + nf * 8 + tig * 2;
            const float* d = acc[mf][nf];
#pragma unroll
            for (int half = 0; half < 2; half++) {
                const int m = r0 + half * 8;
                float2 o = make_float2(d[half * 2], d[half * 2 + 1]);
                o.x += bias[c0]; o.y += bias[c0 + 1];
                *(float2*)(C + (size_t)m * DIM_ + c0) = o;
            }
        }
    }
}

__global__ void k_fill_mem(const float* __restrict__ mk, const float* __restrict__ mv)
{
    int idx = blockIdx.x * blockDim.x + threadIdx.x;      // B*H*M*DH elems
    int d = idx & 63;
    int r = idx >> 6;
    int j  = r % MM_;  r /= MM_;
    int h  = r % H_;
    int b  = r / H_;
    size_t dst = (((size_t)(b * H_ + h)) * J_ + j) * DH_ + d;
    size_t src = ((size_t)h * MM_ + j) * DH_ + d;
    g_k[dst] = mk[src];
    g_v[dst] = mv[src];
}

// ---------------- fused QK^T + head-mix via tf32x3 MMA, double-buffered ----------
__global__ void __launch_bounds__(256, 2) k_dots_mix(const float* __restrict__ pre)
{
    const int b  = blockIdx.z;
    const int i0 = blockIdx.y * 32;
    const int j0 = blockIdx.x * 32;
    if (j0 > i0 + 31 + MM_) return;     // fully above causal band

    __shared__ __align__(16) float Qs[2][32][68];
    __shared__ __align__(16) float Ks[2][32][68];
    __shared__ float Ppre[H_ * H_];

    const int tid  = threadIdx.x;
    const int warp = tid >> 5;
    const int lane = tid & 31;
    const int wi   = warp & 1;
    const int wj   = warp >> 1;
    const int grp  = lane >> 2;
    const int tig  = lane & 3;

    Ppre[tid] = pre[tid];

    const int lr = tid >> 3;
    const int lc = (tid & 7) << 2;
    const int jrow = j0 + lr;
    const bool jvalid = jrow < J_;

    const int ri = wi * 16 + grp;
    const int rj = wj * 8 + grp;

    float acc[H_][4];
#pragma unroll
    for (int ko = 0; ko < H_; ko++)
#pragma unroll
        for (int e = 0; e < 4; e++) acc[ko][e] = 0.f;

    const float* qbase = g_q + ((size_t)b * H_ * N_ + (size_t)(i0 + lr)) * DH_;
    const float* kbase = g_k + ((size_t)b * H_ * J_ + (size_t)jrow) * DH_;
    const size_t qstep = (size_t)N_ * DH_;      // per-head stride
    const size_t kstep = (size_t)J_ * DH_;

    float4 q0r = *(const float4*)(qbase + lc);
    float4 q1r = *(const float4*)(qbase + lc + 32);
    float4 k0r, k1r;
    if (jvalid) {
        k0r = *(const float4*)(kbase + lc);
        k1r = *(const float4*)(kbase + lc + 32);
    } else {
        k0r = make_float4(0.f, 0.f, 0.f, 0.f);
        k1r = k0r;
    }
    *(float4*)&Qs[0][lr][lc]      = q0r;
    *(float4*)&Qs[0][lr][lc + 32] = q1r;
    *(float4*)&Ks[0][lr][lc]      = k0r;
    *(float4*)&Ks[0][lr][lc + 32] = k1r;

#pragma unroll 1
    for (int h = 0; h < H_; h++) {
        const int cb = h & 1;
        if (h + 1 < H_) {
            const float* qn = qbase + (size_t)(h + 1) * qstep;
            q0r = *(const float4*)(qn + lc);
            q1r = *(const float4*)(qn + lc + 32);
            if (jvalid) {
                const float* kn = kbase + (size_t)(h + 1) * kstep;
                k0r = *(const float4*)(kn + lc);
                k1r = *(const float4*)(kn + lc + 32);
            }
        }
        __syncthreads();

        float s0 = 0.f, s1 = 0.f, s2 = 0.f, s3 = 0.f;
#pragma unroll
        for (int k0 = 0; k0 < DH_; k0 += 8) {
            const float a0f = Qs[cb][ri]    [k0 + tig];
            const float a1f = Qs[cb][ri + 8][k0 + tig];
            const float a2f = Qs[cb][ri]    [k0 + tig + 4];
            const float a3f = Qs[cb][ri + 8][k0 + tig + 4];
            const float b0f = Ks[cb][rj][k0 + tig];
            const float b1f = Ks[cb][rj][k0 + tig + 4];

            const unsigned a0h = to_tf32(a0f), a1h = to_tf32(a1f);
            const unsigned a2h = to_tf32(a2f), a3h = to_tf32(a3f);
            const unsigned b0h = to_tf32(b0f), b1h = to_tf32(b1f);
            const unsigned a0l = to_tf32(a0f - __uint_as_float(a0h));
            const unsigned a1l = to_tf32(a1f - __uint_as_float(a1h));
            const unsigned a2l = to_tf32(a2f - __uint_as_float(a2h));
            const unsigned a3l = to_tf32(a3f - __uint_as_float(a3h));
            const unsigned b0l = to_tf32(b0f - __uint_as_float(b0h));
            const unsigned b1l = to_tf32(b1f - __uint_as_float(b1h));

            mma_tf32(s0, s1, s2, s3, a0h, a1h, a2h, a3h, b0h, b1h);   // hi*hi
            mma_tf32(s0, s1, s2, s3, a0l, a1l, a2l, a3l, b0h, b1h);   // lo*hi
            mma_tf32(s0, s1, s2, s3, a0h, a1h, a2h, a3h, b0l, b1l);   // hi*lo
        }

#pragma unroll
        for (int ko = 0; ko < H_; ko++) {
            const float p = Ppre[h * H_ + ko] * SCALE_;
            acc[ko][0] += p * s0; acc[ko][1] += p * s1;
            acc[ko][2] += p * s2; acc[ko][3] += p * s3;
        }

        if (h + 1 < H_) {
            const int nb = cb ^ 1;
            *(float4*)&Qs[nb][lr][lc]      = q0r;
            *(float4*)&Qs[nb][lr][lc + 32] = q1r;
            *(float4*)&Ks[nb][lr][lc]      = k0r;
            *(float4*)&Ks[nb][lr][lc + 32] = k1r;
        }
    }

    const int gi = i0 + ri;
    const int gj = j0 + wj * 8 + tig * 2;
#pragma unroll
    for (int ko = 0; ko < H_; ko++) {
        const size_t base = (((size_t)(b * H_ + ko)) * N_ + gi) * J_ + gj;
        if (gj < J_) {
            g_smix[base]              = acc[ko][0];
            g_smix[base + 8 * J_]     = acc[ko][2];
        }
        if (gj + 1 < J_) {
            g_smix[base + 1]          = acc[ko][1];
            g_smix[base + 8 * J_ + 1] = acc[ko][3];
        }
    }
}

// ---------------- per-row top-k + softmax + sparse A*V ---------------------------
__device__ __forceinline__ unsigned fkey(float f)
{
    unsigned u = __float_as_uint(f);
    return (u & 0x80000000u) ? ~u : (u | 0x80000000u);
}
__device__ __forceinline__ float finv(unsigned k)
{
    return (k & 0x80000000u) ? __uint_as_float(k ^ 0x80000000u)
                             : __uint_as_float(~k);
}

// single-warp suffix-scan over 256 bins; finds bin B with suffix(B) >= kth > suffix(B+1)
__device__ __forceinline__ void scan_bins(const int* hist, int kth, int tid,
                                          int* s_bin, int* s_above)
{
    if (tid < 32) {
        int loc[8];
        int sum = 0;
#pragma unroll
        for (int e = 0; e < 8; e++) { loc[e] = hist[tid * 8 + e]; sum += loc[e]; }
        int v = sum;
#pragma unroll
        for (int o = 1; o < 32; o <<= 1) {
            const int u = __shfl_down_sync(0xffffffffu, v, o);
            if (tid + o < 32) v += u;
        }
        const int after_lane = v - sum;        // count in lanes > tid
        int run = after_lane;
        int sfx[8];
#pragma unroll
        for (int e = 7; e >= 0; e--) { run += loc[e]; sfx[e] = run; }
#pragma unroll
        for (int e = 0; e < 8; e++) {
            const int above = (e == 7) ? after_lane : sfx[e + 1];
            if (sfx[e] >= kth && above < kth) { *s_bin = tid * 8 + e; *s_above = above; }
        }
    }
}

__global__ void __launch_bounds__(256) k_topk_av()
{
    const int i  = blockIdx.x;
    const int ko = blockIdx.y;
    const int b  = blockIdx.z;
    const int tid = threadIdx.x;
    const int lane = tid & 31;
    const int jmax = min(J_, i + MM_ + 1);

    __shared__ unsigned skeysA[J_];          // keys; reused: narrowing buffer; then wgt
    __shared__ unsigned candK[J_];           // candidate keys (bins >= b0), preserved
    __shared__ unsigned narrowA[J_];         // narrowing scratch
    __shared__ unsigned short candI[J_];     // candidate row indices
    __shared__ unsigned short sidx[J_];      // survivor indices
    __shared__ int hist[256];
    __shared__ unsigned redk[8];
    __shared__ float redf[8];
    __shared__ unsigned s_maxk, s_tkey;
    __shared__ float s_sum;
    __shared__ int s_bin, s_above, s_cnt;
    __shared__ float accb[4][64];

    float* wgt = (float*)skeysA;             // alias: valid once keys are dead

    const float* row = g_smix + (((size_t)(b * H_ + ko)) * N_ + i) * J_;

    // --- sweep 1: load keys + top-byte histogram (warp-aggregated atomics) ------
    hist[tid] = 0;
    __syncthreads();
    unsigned lmax = 0u;
    const int nIter = (jmax + 255) >> 8;
    for (int it = 0; it < nIter; it++) {
        const int j = tid + (it << 8);
        const bool valid = j < jmax;
        unsigned k = 0u;
        if (valid) {
            k = fkey(row[j]);
            skeysA[j] = k;
            lmax = max(lmax, k);
        }
        const unsigned bin = valid ? (k >> 24) : 300u;
        const unsigned mmask = __match_any_sync(0xffffffffu, bin);
        if (valid && (mmask & ((1u << lane) - 1u)) == 0u)
            atomicAdd(&hist[bin], __popc(mmask));
    }
#pragma unroll
    for (int o = 16; o > 0; o >>= 1) lmax = max(lmax, __shfl_xor_sync(0xffffffffu, lmax, o));
    if (lane == 0) redk[tid >> 5] = lmax;
    __syncthreads();
    if (tid == 0) {
        unsigned m = redk[0];
#pragma unroll
        for (int w = 1; w < 8; w++) m = max(m, redk[w]);
        s_maxk = m;
    }
    __syncthreads();
    const float vmax = finv(s_maxk);

    float lsum = 0.f;
    int nsurv;

    if (jmax > KTOP_) {
        // --- boundary bin b0 ------------------------------------------------------
        scan_bins(hist, KTOP_, tid, &s_bin, &s_above);
        __syncthreads();
        const unsigned b0 = (unsigned)s_bin;

        // --- sweep 2: scatter all candidates (bins >= b0) with indices -----------
        if (tid == 0) s_cnt = 0;
        __syncthreads();
        for (int j = tid; j < jmax; j += 256) {
            const unsigned k = skeysA[j];
            if ((k >> 24) >= b0) {
                const int p = atomicAdd(&s_cnt, 1);
                candK[p] = k;
                candI[p] = (unsigned short)j;
            }
        }
        __syncthreads();
        const int ncand = s_cnt;

        // --- exact K-th largest among candidates (rank = KTOP_) -------------------
        int c = ncand;
        int kth = KTOP_;
        unsigned* cur = candK;               // never written past here until done
        int shift = 24;
        while (c > 48 && shift >= 0) {
            hist[tid] = 0;
            __syncthreads();
            for (int t = tid; t < c; t += 256)
                atomicAdd(&hist[(cur[t] >> shift) & 255u], 1);
            __syncthreads();
            scan_bins(hist, kth, tid, &s_bin, &s_above);
            __syncthreads();
            const int bsel = s_bin;
            kth -= s_above;
            if (tid == 0) s_cnt = 0;
            __syncthreads();
            unsigned* dst = (cur == narrowA) ? skeysA : narrowA;
            for (int t = tid; t < c; t += 256)
                if (((cur[t] >> shift) & 255u) == (unsigned)bsel)
                    dst[atomicAdd(&s_cnt, 1)] = cur[t];
            __syncthreads();
            c = s_cnt;
            cur = dst;
            shift -= 8;
        }
        if (shift < 0) {
            if (tid == 0) s_tkey = cur[0];     // all remaining keys identical
        } else {
            for (int t = tid; t < c; t += 256) {
                const unsigned x = cur[t];
                int gt = 0, ge = 0;
                for (int u = 0; u < c; u++) { gt += (cur[u] > x); ge += (cur[u] >= x); }
                if (gt < kth && ge >= kth) s_tkey = x;
            }
        }
        __syncthreads();
        const unsigned tkey = s_tkey;

        // --- survivor compaction over the SMALL candidate list --------------------
        if (tid == 0) s_cnt = 0;
        __syncthreads();
        for (int t = tid; t < ncand; t += 256) {
            const unsigned k = candK[t];
            if (k >= tkey) {
                const float w = expf(finv(k) - vmax);
                lsum += w;
                const int q = atomicAdd(&s_cnt, 1);
                wgt[q]  = w;
                sidx[q] = candI[t];
            }
        }
        __syncthreads();
        nsurv = s_cnt;
    } else {
        // tiny rows: everything survives (identity indices; alias-safe per-slot)
        for (int j = tid; j < jmax; j += 256) {
            const float w = expf(finv(skeysA[j]) - vmax);
            wgt[j]  = w;
            sidx[j] = (unsigned short)j;
            lsum += w;
        }
        __syncthreads();
        nsurv = jmax;
    }

    // --- sum of weights ----------------------------------------------------------
#pragma unroll
    for (int o = 16; o > 0; o >>= 1) lsum += __shfl_xor_sync(0xffffffffu, lsum, o);
    if (lane == 0) redf[tid >> 5] = lsum;
    __syncthreads();
    if (tid == 0) {
        float t = 0.f;
#pragma unroll
        for (int w = 0; w < 8; w++) t += redf[w];
        s_sum = t;
    }
    __syncthreads();
    const float sumexp = s_sum;

    // --- gather-weighted sum over surviving v rows -------------------------------
    const int d = tid & 63;
    const int g = tid >> 6;
    float acc = 0.f;
    const float* vb = g_v + ((size_t)(b * H_ + ko)) * J_ * DH_ + d;
    for (int s = g; s < nsurv; s += 4)
        acc += wgt[s] * vb[(size_t)sidx[s] * DH_];
    accb[g][d] = acc;
    __syncthreads();
    if (g == 0) {
        const float tot = accb[0][d] + accb[1][d] + accb[2][d] + accb[3][d];
        g_att[((size_t)(b * N_ + i)) * DIM_ + ko * DH_ + d] = tot / sumexp;
    }
}

// ---------------- launch ---------------------------------------------------------
extern "C" void kernel_launch(void* const* d_in, const int* in_sizes, int n_in,
                              void* d_out, int out_size)
{
    (void)in_sizes; (void)n_in; (void)out_size;
    const float* x    = (const float*)d_in[0];
    const float* Wq   = (const float*)d_in[1];
    const float* Wkv  = (const float*)d_in[2];
    const float* Wo   = (const float*)d_in[3];
    const float* bo   = (const float*)d_in[4];
    const float* pre  = (const float*)d_in[5];
    const float* memk = (const float*)d_in[7];
    const float* memv = (const float*)d_in[8];
    float* out = (float*)d_out;

    k_gemm_qkv<<<dim3(3 * DIM_ / 128, (B_ * N_) / 128), 256>>>(x, Wq, Wkv);
    k_fill_mem<<<(B_ * H_ * MM_ * DH_) / 256, 256>>>(memk, memv);
    k_dots_mix<<<dim3((J_ + 31) / 32, N_ / 32, B_), 256>>>(pre);
    k_topk_av<<<dim3(N_, H_, B_), 256>>>();
    k_gemm_o<<<dim3(DIM_ / 128, (B_ * N_) / 128), 256>>>(Wo, bo, out);
}

// round 12
// speedup vs baseline: 1.2021x; 1.0785x over previous
#include <cuda_runtime.h>
#include <cstdint>
#include <cstddef>

#define B_    2
#define N_    2048
#define DIM_  1024
#define H_    16
#define DH_   64
#define MM_   16
#define J_    2064          // N_ + MM_
#define KTOP_ 64
#define SCALE_ 0.125f

// ---------------- static device scratch ----------------
__device__ float g_q   [(size_t)B_*H_*N_*DH_];      // (b,h,i,d)
__device__ float g_k   [(size_t)B_*H_*J_*DH_];      // (b,h,j,d), j<M = mem
__device__ float g_v   [(size_t)B_*H_*J_*DH_];
__device__ float g_smix[(size_t)B_*H_*N_*J_];       // mixed scores (b,k,i,j)
__device__ float g_att [(size_t)B_*N_*DIM_];        // attention output (b,i,k*64+d)

// ---------------- tf32 MMA helpers -----------------------------------------------
__device__ __forceinline__ unsigned to_tf32(float x)
{
    unsigned r;
    asm("cvt.rna.tf32.f32 %0, %1;" : "=r"(r) : "f"(x));
    return r;
}

__device__ __forceinline__ void mma_tf32(float& d0, float& d1, float& d2, float& d3,
                                         unsigned a0, unsigned a1, unsigned a2, unsigned a3,
                                         unsigned b0, unsigned b1)
{
    asm volatile("mma.sync.aligned.m16n8k8.row.col.f32.tf32.tf32.f32 "
                 "{%0,%1,%2,%3}, {%4,%5,%6,%7}, {%8,%9}, {%0,%1,%2,%3};\n"
                 : "+f"(d0), "+f"(d1), "+f"(d2), "+f"(d3)
                 : "r"(a0), "r"(a1), "r"(a2), "r"(a3), "r"(b0), "r"(b1));
}

__device__ __forceinline__ unsigned smem_u32(const void* p)
{
    return (unsigned)__cvta_generic_to_shared(p);
}
#define CP16(dst, src) asm volatile("cp.async.cg.shared.global [%0], [%1], 16;" :: "r"(dst), "l"(src))
#define CP_COMMIT()    asm volatile("cp.async.commit_group;")
#define CP_WAIT1()     asm volatile("cp.async.wait_group 1;")

// ======= 128x128 / BK=16 tf32x3 GEMM, 2-stage cp.async smem pipeline =============
struct GemmSmem {
    float As[2][128][20];   // [stage][m][k]  banks: 20*grp+tig -> conflict-free
    float Bs[2][16][136];   // [stage][k][n]  banks: 8*tig+grp  -> conflict-free
};

__device__ __forceinline__ void gemm_tiles(GemmSmem& S,
                                           const float* __restrict__ Aeff,
                                           const float* __restrict__ Bm,
                                           int Ndim, int Kdim,
                                           int m0, int n0,
                                           float acc[4][4][4])
{
    const int tid  = threadIdx.x;
    const int warp = tid >> 5;
    const int lane = tid & 31;
    const int wm   = warp & 1;
    const int wn   = warp >> 1;
    const int grp  = lane >> 2;
    const int tig  = lane & 3;

    const int arow  = tid >> 1;          // 0..127
    const int acol8 = (tid & 1) * 8;     // 0 or 8
    const int brow  = tid >> 4;          // 0..15
    const int bcol8 = (tid & 15) * 8;    // 0..120

    const float* ag = Aeff + (size_t)(m0 + arow) * Kdim + acol8;
    const float* bg = Bm + n0 + bcol8;

    unsigned a_dst[2], b_dst[2];
    a_dst[0] = smem_u32(&S.As[0][arow][acol8]);
    a_dst[1] = smem_u32(&S.As[1][arow][acol8]);
    b_dst[0] = smem_u32(&S.Bs[0][brow][bcol8]);
    b_dst[1] = smem_u32(&S.Bs[1][brow][bcol8]);

    // prologue: stage 0
    CP16(a_dst[0],      ag);
    CP16(a_dst[0] + 16, ag + 4);
    CP16(b_dst[0],      bg + (size_t)brow * Ndim);
    CP16(b_dst[0] + 16, bg + (size_t)brow * Ndim + 4);
    CP_COMMIT();

    int s = 0;
    for (int k0 = 0; k0 < Kdim; k0 += 16, s ^= 1) {
        if (k0 + 16 < Kdim) {
            const int ns = s ^ 1;
            CP16(a_dst[ns],      ag + k0 + 16);
            CP16(a_dst[ns] + 16, ag + k0 + 20);
            CP16(b_dst[ns],      bg + (size_t)(k0 + 16 + brow) * Ndim);
            CP16(b_dst[ns] + 16, bg + (size_t)(k0 + 16 + brow) * Ndim + 4);
        }
        CP_COMMIT();
        CP_WAIT1();
        __syncthreads();

#pragma unroll
        for (int ks = 0; ks < 2; ks++) {
            const int kk = ks * 8 + tig;
            unsigned ah[4][4], al[4][4], bh[4][2], bl[4][2];
#pragma unroll
            for (int nf = 0; nf < 4; nf++) {
                const int col = wn * 32 + nf * 8 + grp;
                const float b0f = S.Bs[s][kk][col];
                const float b1f = S.Bs[s][kk + 4][col];
                bh[nf][0] = to_tf32(b0f);
                bh[nf][1] = to_tf32(b1f);
                bl[nf][0] = to_tf32(b0f - __uint_as_float(bh[nf][0]));
                bl[nf][1] = to_tf32(b1f - __uint_as_float(bh[nf][1]));
            }
#pragma unroll
            for (int mf = 0; mf < 4; mf++) {
                const int row = wm * 64 + mf * 16 + grp;
                const float a0f = S.As[s][row][kk];
                const float a1f = S.As[s][row + 8][kk];
                const float a2f = S.As[s][row][kk + 4];
                const float a3f = S.As[s][row + 8][kk + 4];
                ah[mf][0] = to_tf32(a0f); ah[mf][1] = to_tf32(a1f);
                ah[mf][2] = to_tf32(a2f); ah[mf][3] = to_tf32(a3f);
                al[mf][0] = to_tf32(a0f - __uint_as_float(ah[mf][0]));
                al[mf][1] = to_tf32(a1f - __uint_as_float(ah[mf][1]));
                al[mf][2] = to_tf32(a2f - __uint_as_float(ah[mf][2]));
                al[mf][3] = to_tf32(a3f - __uint_as_float(ah[mf][3]));
            }
#pragma unroll
            for (int mf = 0; mf < 4; mf++)
#pragma unroll
                for (int nf = 0; nf < 4; nf++) {
                    float* d = acc[mf][nf];
                    mma_tf32(d[0], d[1], d[2], d[3],
                             ah[mf][0], ah[mf][1], ah[mf][2], ah[mf][3],
                             bh[nf][0], bh[nf][1]);
                    mma_tf32(d[0], d[1], d[2], d[3],
                             al[mf][0], al[mf][1], al[mf][2], al[mf][3],
                             bh[nf][0], bh[nf][1]);
                    mma_tf32(d[0], d[1], d[2], d[3],
                             ah[mf][0], ah[mf][1], ah[mf][2], ah[mf][3],
                             bl[nf][0], bl[nf][1]);
                }
        }
        __syncthreads();
    }
}

// ---- merged Q/KV projection: grid.x = 24 tiles over [Wq | Wkv] columns ----------
__global__ void __launch_bounds__(256) k_gemm_qkv(const float* __restrict__ x,
                                                  const float* __restrict__ Wq,
                                                  const float* __restrict__ Wkv)
{
    __shared__ GemmSmem S;

    const int n0g = blockIdx.x * 128;        // 0..3071
    const int m0  = blockIdx.y * 128;
    const bool isQ = n0g < DIM_;
    const float* Bm = isQ ? Wq : Wkv;
    const int Ndim  = isQ ? DIM_ : 2 * DIM_;
    const int n0    = isQ ? n0g : n0g - DIM_;

    float acc[4][4][4];
#pragma unroll
    for (int mf = 0; mf < 4; mf++)
#pragma unroll
        for (int nf = 0; nf < 4; nf++)
#pragma unroll
            for (int e = 0; e < 4; e++) acc[mf][nf][e] = 0.f;

    gemm_tiles(S, x, Bm, Ndim, DIM_, m0, n0, acc);

    const int tid  = threadIdx.x;
    const int warp = tid >> 5;
    const int lane = tid & 31;
    const int wm   = warp & 1;
    const int wn   = warp >> 1;
    const int grp  = lane >> 2;
    const int tig  = lane & 3;

#pragma unroll
    for (int mf = 0; mf < 4; mf++) {
        const int r0 = m0 + wm * 64 + mf * 16 + grp;
#pragma unroll
        for (int nf = 0; nf < 4; nf++) {
            const int c0 = n0 + wn * 32 + nf * 8 + tig * 2;
            const float* d = acc[mf][nf];
#pragma unroll
            for (int half = 0; half < 2; half++) {
                const int m = r0 + half * 8;
                const float2 o = make_float2(d[half * 2], d[half * 2 + 1]);
                const int b = m >> 11;
                const int i = m & (N_ - 1);
                if (isQ) {
                    const int h = c0 >> 6, dd = c0 & 63;
                    *(float2*)(g_q + (((size_t)(b * H_ + h)) * N_ + i) * DH_ + dd) = o;
                } else if (c0 < DIM_) {
                    const int h = c0 >> 6, dd = c0 & 63;
                    *(float2*)(g_k + (((size_t)(b * H_ + h)) * J_ + MM_ + i) * DH_ + dd) = o;
                } else {
                    const int c = c0 - DIM_;
                    const int h = c >> 6, dd = c & 63;
                    *(float2*)(g_v + (((size_t)(b * H_ + h)) * J_ + MM_ + i) * DH_ + dd) = o;
                }
            }
        }
    }
}

// ---- output projection: C = g_att @ Wo + bo -------------------------------------
__global__ void __launch_bounds__(256) k_gemm_o(const float* __restrict__ Wo,
                                                const float* __restrict__ bias,
                                                float* __restrict__ C)
{
    __shared__ GemmSmem S;

    const int m0 = blockIdx.y * 128;
    const int n0 = blockIdx.x * 128;

    float acc[4][4][4];
#pragma unroll
    for (int mf = 0; mf < 4; mf++)
#pragma unroll
        for (int nf = 0; nf < 4; nf++)
#pragma unroll
            for (int e = 0; e < 4; e++) acc[mf][nf][e] = 0.f;

    gemm_tiles(S, g_att, Wo, DIM_, DIM_, m0, n0, acc);

    const int tid  = threadIdx.x;
    const int warp = tid >> 5;
    const int lane = tid & 31;
    const int wm   = warp & 1;
    const int wn   = warp >> 1;
    const int grp  = lane >> 2;
    const int tig  = lane & 3;

#pragma unroll
    for (int mf = 0; mf < 4; mf++) {
        const int r0 = m0 + wm * 64 + mf * 16 + grp;
#pragma unroll
        for (int nf = 0; nf < 4; nf++) {
            const int c0 = n0 + wn * 32 + nf * 8 + tig * 2;
            const float* d = acc[mf][nf];
#pragma unroll
            for (int half = 0; half < 2; half++) {
                const int m = r0 + half * 8;
                float2 o = make_float2(d[half * 2], d[half * 2 + 1]);
                o.x += bias[c0]; o.y += bias[c0 + 1];
                *(float2*)(C + (size_t)m * DIM_ + c0) = o;
            }
        }
    }
}

__global__ void k_fill_mem(const float* __restrict__ mk, const float* __restrict__ mv)
{
    int idx = blockIdx.x * blockDim.x + threadIdx.x;      // B*H*M*DH elems
    int d = idx & 63;
    int r = idx >> 6;
    int j  = r % MM_;  r /= MM_;
    int h  = r % H_;
    int b  = r / H_;
    size_t dst = (((size_t)(b * H_ + h)) * J_ + j) * DH_ + d;
    size_t src = ((size_t)h * MM_ + j) * DH_ + d;
    g_k[dst] = mk[src];
    g_v[dst] = mv[src];
}

// ---------------- fused QK^T + head-mix via tf32x3 MMA, double-buffered ----------
__global__ void __launch_bounds__(256, 2) k_dots_mix(const float* __restrict__ pre)
{
    const int b  = blockIdx.z;
    const int i0 = blockIdx.y * 32;
    const int j0 = blockIdx.x * 32;
    if (j0 > i0 + 31 + MM_) return;     // fully above causal band

    __shared__ __align__(16) float Qs[2][32][68];
    __shared__ __align__(16) float Ks[2][32][68];
    __shared__ float Ppre[H_ * H_];

    const int tid  = threadIdx.x;
    const int warp = tid >> 5;
    const int lane = tid & 31;
    const int wi   = warp & 1;
    const int wj   = warp >> 1;
    const int grp  = lane >> 2;
    const int tig  = lane & 3;

    Ppre[tid] = pre[tid];

    const int lr = tid >> 3;
    const int lc = (tid & 7) << 2;
    const int jrow = j0 + lr;
    const bool jvalid = jrow < J_;

    const int ri = wi * 16 + grp;
    const int rj = wj * 8 + grp;

    float acc[H_][4];
#pragma unroll
    for (int ko = 0; ko < H_; ko++)
#pragma unroll
        for (int e = 0; e < 4; e++) acc[ko][e] = 0.f;

    const float* qbase = g_q + ((size_t)b * H_ * N_ + (size_t)(i0 + lr)) * DH_;
    const float* kbase = g_k + ((size_t)b * H_ * J_ + (size_t)jrow) * DH_;
    const size_t qstep = (size_t)N_ * DH_;      // per-head stride
    const size_t kstep = (size_t)J_ * DH_;

    float4 q0r = *(const float4*)(qbase + lc);
    float4 q1r = *(const float4*)(qbase + lc + 32);
    float4 k0r, k1r;
    if (jvalid) {
        k0r = *(const float4*)(kbase + lc);
        k1r = *(const float4*)(kbase + lc + 32);
    } else {
        k0r = make_float4(0.f, 0.f, 0.f, 0.f);
        k1r = k0r;
    }
    *(float4*)&Qs[0][lr][lc]      = q0r;
    *(float4*)&Qs[0][lr][lc + 32] = q1r;
    *(float4*)&Ks[0][lr][lc]      = k0r;
    *(float4*)&Ks[0][lr][lc + 32] = k1r;

#pragma unroll 1
    for (int h = 0; h < H_; h++) {
        const int cb = h & 1;
        if (h + 1 < H_) {
            const float* qn = qbase + (size_t)(h + 1) * qstep;
            q0r = *(const float4*)(qn + lc);
            q1r = *(const float4*)(qn + lc + 32);
            if (jvalid) {
                const float* kn = kbase + (size_t)(h + 1) * kstep;
                k0r = *(const float4*)(kn + lc);
                k1r = *(const float4*)(kn + lc + 32);
            }
        }
        __syncthreads();

        float s0 = 0.f, s1 = 0.f, s2 = 0.f, s3 = 0.f;
#pragma unroll
        for (int k0 = 0; k0 < DH_; k0 += 8) {
            const float a0f = Qs[cb][ri]    [k0 + tig];
            const float a1f = Qs[cb][ri + 8][k0 + tig];
            const float a2f = Qs[cb][ri]    [k0 + tig + 4];
            const float a3f = Qs[cb][ri + 8][k0 + tig + 4];
            const float b0f = Ks[cb][rj][k0 + tig];
            const float b1f = Ks[cb][rj][k0 + tig + 4];

            const unsigned a0h = to_tf32(a0f), a1h = to_tf32(a1f);
            const unsigned a2h = to_tf32(a2f), a3h = to_tf32(a3f);
            const unsigned b0h = to_tf32(b0f), b1h = to_tf32(b1f);
            const unsigned a0l = to_tf32(a0f - __uint_as_float(a0h));
            const unsigned a1l = to_tf32(a1f - __uint_as_float(a1h));
            const unsigned a2l = to_tf32(a2f - __uint_as_float(a2h));
            const unsigned a3l = to_tf32(a3f - __uint_as_float(a3h));
            const unsigned b0l = to_tf32(b0f - __uint_as_float(b0h));
            const unsigned b1l = to_tf32(b1f - __uint_as_float(b1h));

            mma_tf32(s0, s1, s2, s3, a0h, a1h, a2h, a3h, b0h, b1h);   // hi*hi
            mma_tf32(s0, s1, s2, s3, a0l, a1l, a2l, a3l, b0h, b1h);   // lo*hi
            mma_tf32(s0, s1, s2, s3, a0h, a1h, a2h, a3h, b0l, b1l);   // hi*lo
        }

#pragma unroll
        for (int ko = 0; ko < H_; ko++) {
            const float p = Ppre[h * H_ + ko] * SCALE_;
            acc[ko][0] += p * s0; acc[ko][1] += p * s1;
            acc[ko][2] += p * s2; acc[ko][3] += p * s3;
        }

        if (h + 1 < H_) {
            const int nb = cb ^ 1;
            *(float4*)&Qs[nb][lr][lc]      = q0r;
            *(float4*)&Qs[nb][lr][lc + 32] = q1r;
            *(float4*)&Ks[nb][lr][lc]      = k0r;
            *(float4*)&Ks[nb][lr][lc + 32] = k1r;
        }
    }

    const int gi = i0 + ri;
    const int gj = j0 + wj * 8 + tig * 2;
#pragma unroll
    for (int ko = 0; ko < H_; ko++) {
        const size_t base = (((size_t)(b * H_ + ko)) * N_ + gi) * J_ + gj;
        if (gj < J_) {
            g_smix[base]              = acc[ko][0];
            g_smix[base + 8 * J_]     = acc[ko][2];
        }
        if (gj + 1 < J_) {
            g_smix[base + 1]          = acc[ko][1];
            g_smix[base + 8 * J_ + 1] = acc[ko][3];
        }
    }
}

// ---------------- per-row top-k + softmax + sparse A*V (round-10 body) -----------
__device__ __forceinline__ unsigned fkey(float f)
{
    unsigned u = __float_as_uint(f);
    return (u & 0x80000000u) ? ~u : (u | 0x80000000u);
}
__device__ __forceinline__ float finv(unsigned k)
{
    return (k & 0x80000000u) ? __uint_as_float(k ^ 0x80000000u)
                             : __uint_as_float(~k);
}

// single-warp suffix-scan over 256 bins; finds bin B with suffix(B) >= kth > suffix(B+1)
__device__ __forceinline__ void scan_bins(const int* hist, int kth, int tid,
                                          int* s_bin, int* s_above)
{
    if (tid < 32) {
        int loc[8];
        int sum = 0;
#pragma unroll
        for (int e = 0; e < 8; e++) { loc[e] = hist[tid * 8 + e]; sum += loc[e]; }
        int v = sum;
#pragma unroll
        for (int o = 1; o < 32; o <<= 1) {
            const int u = __shfl_down_sync(0xffffffffu, v, o);
            if (tid + o < 32) v += u;
        }
        const int after_lane = v - sum;        // count in lanes > tid
        int run = after_lane;
        int sfx[8];
#pragma unroll
        for (int e = 7; e >= 0; e--) { run += loc[e]; sfx[e] = run; }
#pragma unroll
        for (int e = 0; e < 8; e++) {
            const int above = (e == 7) ? after_lane : sfx[e + 1];
            if (sfx[e] >= kth && above < kth) { *s_bin = tid * 8 + e; *s_above = above; }
        }
    }
}

__global__ void __launch_bounds__(256) k_topk_av()
{
    const int i  = blockIdx.x;
    const int ko = blockIdx.y;
    const int b  = blockIdx.z;
    const int tid = threadIdx.x;
    const int lane = tid & 31;
    const int jmax = min(J_, i + MM_ + 1);

    __shared__ unsigned skeys[J_];
    __shared__ int   sidx[J_];       // survivor indices; reused as candB
    __shared__ float swgt[J_];       // survivor weights; reused as candA
    __shared__ int   hist[256];
    __shared__ unsigned redk[8];
    __shared__ float redf[8];
    __shared__ unsigned s_maxk, s_tkey;
    __shared__ float s_sum;
    __shared__ int   s_bin, s_above, s_cnt;
    __shared__ float accb[4][64];

    const float* row = g_smix + (((size_t)(b * H_ + ko)) * N_ + i) * J_;

    // --- load sweep fused with top-byte histogram (warp-aggregated atomics) -----
    hist[tid] = 0;
    __syncthreads();
    unsigned lmax = 0u;
    const int nIter = (jmax + 255) >> 8;
    for (int it = 0; it < nIter; it++) {
        const int j = tid + (it << 8);
        const bool valid = j < jmax;
        unsigned k = 0u;
        if (valid) {
            k = fkey(row[j]);
            skeys[j] = k;
            lmax = max(lmax, k);
        }
        const unsigned bin = valid ? (k >> 24) : 300u;     // sentinel for invalid
        const unsigned mmask = __match_any_sync(0xffffffffu, bin);
        if (valid && (mmask & ((1u << lane) - 1u)) == 0u)  // lowest lane = leader
            atomicAdd(&hist[bin], __popc(mmask));
    }
#pragma unroll
    for (int o = 16; o > 0; o >>= 1) lmax = max(lmax, __shfl_xor_sync(0xffffffffu, lmax, o));
    if (lane == 0) redk[tid >> 5] = lmax;
    __syncthreads();
    if (tid == 0) {
        unsigned m = redk[0];
#pragma unroll
        for (int w = 1; w < 8; w++) m = max(m, redk[w]);
        s_maxk = m;
    }
    __syncthreads();
    const float vmax = finv(s_maxk);

    // --- exact K-th largest key: bin scan + boundary-bin candidate select -------
    unsigned tkey = 0u;
    if (jmax > KTOP_) {
        scan_bins(hist, KTOP_, tid, &s_bin, &s_above);
        __syncthreads();
        const int b0 = s_bin;
        int kth = KTOP_ - s_above;

        if (tid == 0) s_cnt = 0;
        __syncthreads();
        unsigned* candA = (unsigned*)swgt;
        unsigned* candB = (unsigned*)sidx;
        for (int j = tid; j < jmax; j += 256) {
            const unsigned k = skeys[j];
            if ((k >> 24) == (unsigned)b0) candA[atomicAdd(&s_cnt, 1)] = k;
        }
        __syncthreads();
        int c = s_cnt;
        unsigned* cur = candA;
        unsigned* alt = candB;
        int shift = 16;
        while (c > 48 && shift >= 0) {
            hist[tid] = 0;
            __syncthreads();
            for (int t = tid; t < c; t += 256)
                atomicAdd(&hist[(cur[t] >> shift) & 255u], 1);
            __syncthreads();
            scan_bins(hist, kth, tid, &s_bin, &s_above);
            __syncthreads();
            const int bsel = s_bin;
            kth -= s_above;
            if (tid == 0) s_cnt = 0;
            __syncthreads();
            for (int t = tid; t < c; t += 256)
                if (((cur[t] >> shift) & 255u) == (unsigned)bsel)
                    alt[atomicAdd(&s_cnt, 1)] = cur[t];
            __syncthreads();
            c = s_cnt;
            unsigned* tmp = cur; cur = alt; alt = tmp;
            shift -= 8;
        }
        if (shift < 0) {
            if (tid == 0) s_tkey = cur[0];          // all remaining keys identical
        } else {
            // exact rank-count select among c (<=48) candidates
            for (int t = tid; t < c; t += 256) {
                const unsigned x = cur[t];
                int gt = 0, ge = 0;
                for (int u = 0; u < c; u++) { gt += (cur[u] > x); ge += (cur[u] >= x); }
                if (gt < kth && ge >= kth) s_tkey = x;
            }
        }
        __syncthreads();
        tkey = s_tkey;
    }

    // --- compact survivors + deterministic exp-sum ------------------------------
    if (tid == 0) s_cnt = 0;
    __syncthreads();
    float lsum = 0.f;
    for (int j = tid; j < jmax; j += 256) {
        const unsigned k = skeys[j];
        if (k >= tkey) {
            const float w = __expf(finv(k) - vmax);
            lsum += w;
            const int p = atomicAdd(&s_cnt, 1);
            sidx[p] = j;
            swgt[p] = w;
        }
    }
#pragma unroll
    for (int o = 16; o > 0; o >>= 1) lsum += __shfl_xor_sync(0xffffffffu, lsum, o);
    if (lane == 0) redf[tid >> 5] = lsum;
    __syncthreads();
    if (tid == 0) {
        float t = 0.f;
#pragma unroll
        for (int w = 0; w < 8; w++) t += redf[w];
        s_sum = t;
    }
    __syncthreads();
    const float sumexp = s_sum;
    const int nsurv = s_cnt;

    // --- gather-weighted sum over surviving v rows ------------------------------
    const int d = tid & 63;
    const int g = tid >> 6;
    float acc = 0.f;
    const float* vb = g_v + ((size_t)(b * H_ + ko)) * J_ * DH_ + d;
    for (int s = g; s < nsurv; s += 4)
        acc += swgt[s] * vb[(size_t)sidx[s] * DH_];
    accb[g][d] = acc;
    __syncthreads();
    if (g == 0) {
        const float tot = accb[0][d] + accb[1][d] + accb[2][d] + accb[3][d];
        g_att[((size_t)(b * N_ + i)) * DIM_ + ko * DH_ + d] = tot / sumexp;
    }
}

// ---------------- launch ---------------------------------------------------------
extern "C" void kernel_launch(void* const* d_in, const int* in_sizes, int n_in,
                              void* d_out, int out_size)
{
    (void)in_sizes; (void)n_in; (void)out_size;
    const float* x    = (const float*)d_in[0];
    const float* Wq   = (const float*)d_in[1];
    const float* Wkv  = (const float*)d_in[2];
    const float* Wo   = (const float*)d_in[3];
    const float* bo   = (const float*)d_in[4];
    const float* pre  = (const float*)d_in[5];
    const float* memk = (const float*)d_in[7];
    const float* memv = (const float*)d_in[8];
    float* out = (float*)d_out;

    k_gemm_qkv<<<dim3(3 * DIM_ / 128, (B_ * N_) / 128), 256>>>(x, Wq, Wkv);
    k_fill_mem<<<(B_ * H_ * MM_ * DH_) / 256, 256>>>(memk, memv);
    k_dots_mix<<<dim3((J_ + 31) / 32, N_ / 32, B_), 256>>>(pre);
    k_topk_av<<<dim3(N_, H_, B_), 256>>>();
    k_gemm_o<<<dim3(DIM_ / 128, (B_ * N_) / 128), 256>>>(Wo, bo, out);
}

// round 13
// speedup vs baseline: 1.2399x; 1.0314x over previous
#include <cuda_runtime.h>
#include <cstdint>
#include <cstddef>

#define B_    2
#define N_    2048
#define DIM_  1024
#define H_    16
#define DH_   64
#define MM_   16
#define J_    2064          // N_ + MM_
#define KTOP_ 64
#define SCALE_ 0.125f

// ---------------- static device scratch ----------------
__device__ float g_q   [(size_t)B_*H_*N_*DH_];      // (b,h,i,d)
__device__ float g_k   [(size_t)B_*H_*J_*DH_];      // (b,h,j,d), j<M = mem
__device__ float g_v   [(size_t)B_*H_*J_*DH_];
__device__ float g_smix[(size_t)B_*H_*N_*J_];       // mixed scores (b,k,i,j)
__device__ float g_att [(size_t)B_*N_*DIM_];        // attention output (b,i,k*64+d)

// ---------------- tf32 MMA helpers -----------------------------------------------
__device__ __forceinline__ unsigned to_tf32(float x)
{
    unsigned r;
    asm("cvt.rna.tf32.f32 %0, %1;" : "=r"(r) : "f"(x));
    return r;
}

__device__ __forceinline__ void mma_tf32(float& d0, float& d1, float& d2, float& d3,
                                         unsigned a0, unsigned a1, unsigned a2, unsigned a3,
                                         unsigned b0, unsigned b1)
{
    asm volatile("mma.sync.aligned.m16n8k8.row.col.f32.tf32.tf32.f32 "
                 "{%0,%1,%2,%3}, {%4,%5,%6,%7}, {%8,%9}, {%0,%1,%2,%3};\n"
                 : "+f"(d0), "+f"(d1), "+f"(d2), "+f"(d3)
                 : "r"(a0), "r"(a1), "r"(a2), "r"(a3), "r"(b0), "r"(b1));
}

__device__ __forceinline__ unsigned smem_u32(const void* p)
{
    return (unsigned)__cvta_generic_to_shared(p);
}
#define CP16(dst, src) asm volatile("cp.async.cg.shared.global [%0], [%1], 16;" :: "r"(dst), "l"(src))
#define CP_COMMIT()    asm volatile("cp.async.commit_group;")
#define CP_WAIT1()     asm volatile("cp.async.wait_group 1;")

// ======= 128x128 / BK=16 tf32x3 GEMM, 2-stage cp.async smem pipeline =============
struct GemmSmem {
    float As[2][128][20];   // [stage][m][k]  banks: 20*grp+tig -> conflict-free
    float Bs[2][16][136];   // [stage][k][n]  banks: 8*tig+grp  -> conflict-free
};

__device__ __forceinline__ void gemm_tiles(GemmSmem& S,
                                           const float* __restrict__ Aeff,
                                           const float* __restrict__ Bm,
                                           int Ndim, int Kdim,
                                           int m0, int n0,
                                           float acc[4][4][4])
{
    const int tid  = threadIdx.x;
    const int warp = tid >> 5;
    const int lane = tid & 31;
    const int wm   = warp & 1;
    const int wn   = warp >> 1;
    const int grp  = lane >> 2;
    const int tig  = lane & 3;

    const int arow  = tid >> 1;          // 0..127
    const int acol8 = (tid & 1) * 8;     // 0 or 8
    const int brow  = tid >> 4;          // 0..15
    const int bcol8 = (tid & 15) * 8;    // 0..120

    const float* ag = Aeff + (size_t)(m0 + arow) * Kdim + acol8;
    const float* bg = Bm + n0 + bcol8;

    unsigned a_dst[2], b_dst[2];
    a_dst[0] = smem_u32(&S.As[0][arow][acol8]);
    a_dst[1] = smem_u32(&S.As[1][arow][acol8]);
    b_dst[0] = smem_u32(&S.Bs[0][brow][bcol8]);
    b_dst[1] = smem_u32(&S.Bs[1][brow][bcol8]);

    // prologue: stage 0
    CP16(a_dst[0],      ag);
    CP16(a_dst[0] + 16, ag + 4);
    CP16(b_dst[0],      bg + (size_t)brow * Ndim);
    CP16(b_dst[0] + 16, bg + (size_t)brow * Ndim + 4);
    CP_COMMIT();

    int s = 0;
    for (int k0 = 0; k0 < Kdim; k0 += 16, s ^= 1) {
        if (k0 + 16 < Kdim) {
            const int ns = s ^ 1;
            CP16(a_dst[ns],      ag + k0 + 16);
            CP16(a_dst[ns] + 16, ag + k0 + 20);
            CP16(b_dst[ns],      bg + (size_t)(k0 + 16 + brow) * Ndim);
            CP16(b_dst[ns] + 16, bg + (size_t)(k0 + 16 + brow) * Ndim + 4);
        }
        CP_COMMIT();
        CP_WAIT1();
        __syncthreads();

#pragma unroll
        for (int ks = 0; ks < 2; ks++) {
            const int kk = ks * 8 + tig;
            unsigned ah[4][4], al[4][4], bh[4][2], bl[4][2];
#pragma unroll
            for (int nf = 0; nf < 4; nf++) {
                const int col = wn * 32 + nf * 8 + grp;
                const float b0f = S.Bs[s][kk][col];
                const float b1f = S.Bs[s][kk + 4][col];
                bh[nf][0] = to_tf32(b0f);
                bh[nf][1] = to_tf32(b1f);
                bl[nf][0] = to_tf32(b0f - __uint_as_float(bh[nf][0]));
                bl[nf][1] = to_tf32(b1f - __uint_as_float(bh[nf][1]));
            }
#pragma unroll
            for (int mf = 0; mf < 4; mf++) {
                const int row = wm * 64 + mf * 16 + grp;
                const float a0f = S.As[s][row][kk];
                const float a1f = S.As[s][row + 8][kk];
                const float a2f = S.As[s][row][kk + 4];
                const float a3f = S.As[s][row + 8][kk + 4];
                ah[mf][0] = to_tf32(a0f); ah[mf][1] = to_tf32(a1f);
                ah[mf][2] = to_tf32(a2f); ah[mf][3] = to_tf32(a3f);
                al[mf][0] = to_tf32(a0f - __uint_as_float(ah[mf][0]));
                al[mf][1] = to_tf32(a1f - __uint_as_float(ah[mf][1]));
                al[mf][2] = to_tf32(a2f - __uint_as_float(ah[mf][2]));
                al[mf][3] = to_tf32(a3f - __uint_as_float(ah[mf][3]));
            }
#pragma unroll
            for (int mf = 0; mf < 4; mf++)
#pragma unroll
                for (int nf = 0; nf < 4; nf++) {
                    float* d = acc[mf][nf];
                    mma_tf32(d[0], d[1], d[2], d[3],
                             ah[mf][0], ah[mf][1], ah[mf][2], ah[mf][3],
                             bh[nf][0], bh[nf][1]);
                    mma_tf32(d[0], d[1], d[2], d[3],
                             al[mf][0], al[mf][1], al[mf][2], al[mf][3],
                             bh[nf][0], bh[nf][1]);
                    mma_tf32(d[0], d[1], d[2], d[3],
                             ah[mf][0], ah[mf][1], ah[mf][2], ah[mf][3],
                             bl[nf][0], bl[nf][1]);
                }
        }
        __syncthreads();
    }
}

// ---- merged Q/KV projection: grid.x = 24 tiles over [Wq | Wkv] columns ----------
__global__ void __launch_bounds__(256) k_gemm_qkv(const float* __restrict__ x,
                                                  const float* __restrict__ Wq,
                                                  const float* __restrict__ Wkv)
{
    __shared__ GemmSmem S;

    const int n0g = blockIdx.x * 128;        // 0..3071
    const int m0  = blockIdx.y * 128;
    const bool isQ = n0g < DIM_;
    const float* Bm = isQ ? Wq : Wkv;
    const int Ndim  = isQ ? DIM_ : 2 * DIM_;
    const int n0    = isQ ? n0g : n0g - DIM_;

    float acc[4][4][4];
#pragma unroll
    for (int mf = 0; mf < 4; mf++)
#pragma unroll
        for (int nf = 0; nf < 4; nf++)
#pragma unroll
            for (int e = 0; e < 4; e++) acc[mf][nf][e] = 0.f;

    gemm_tiles(S, x, Bm, Ndim, DIM_, m0, n0, acc);

    const int tid  = threadIdx.x;
    const int warp = tid >> 5;
    const int lane = tid & 31;
    const int wm   = warp & 1;
    const int wn   = warp >> 1;
    const int grp  = lane >> 2;
    const int tig  = lane & 3;

#pragma unroll
    for (int mf = 0; mf < 4; mf++) {
        const int r0 = m0 + wm * 64 + mf * 16 + grp;
#pragma unroll
        for (int nf = 0; nf < 4; nf++) {
            const int c0 = n0 + wn * 32 + nf * 8 + tig * 2;
            const float* d = acc[mf][nf];
#pragma unroll
            for (int half = 0; half < 2; half++) {
                const int m = r0 + half * 8;
                const float2 o = make_float2(d[half * 2], d[half * 2 + 1]);
                const int b = m >> 11;
                const int i = m & (N_ - 1);
                if (isQ) {
                    const int h = c0 >> 6, dd = c0 & 63;
                    *(float2*)(g_q + (((size_t)(b * H_ + h)) * N_ + i) * DH_ + dd) = o;
                } else if (c0 < DIM_) {
                    const int h = c0 >> 6, dd = c0 & 63;
                    *(float2*)(g_k + (((size_t)(b * H_ + h)) * J_ + MM_ + i) * DH_ + dd) = o;
                } else {
                    const int c = c0 - DIM_;
                    const int h = c >> 6, dd = c & 63;
                    *(float2*)(g_v + (((size_t)(b * H_ + h)) * J_ + MM_ + i) * DH_ + dd) = o;
                }
            }
        }
    }
}

// ---- output projection: C = g_att @ Wo + bo -------------------------------------
__global__ void __launch_bounds__(256) k_gemm_o(const float* __restrict__ Wo,
                                                const float* __restrict__ bias,
                                                float* __restrict__ C)
{
    __shared__ GemmSmem S;

    const int m0 = blockIdx.y * 128;
    const int n0 = blockIdx.x * 128;

    float acc[4][4][4];
#pragma unroll
    for (int mf = 0; mf < 4; mf++)
#pragma unroll
        for (int nf = 0; nf < 4; nf++)
#pragma unroll
            for (int e = 0; e < 4; e++) acc[mf][nf][e] = 0.f;

    gemm_tiles(S, g_att, Wo, DIM_, DIM_, m0, n0, acc);

    const int tid  = threadIdx.x;
    const int warp = tid >> 5;
    const int lane = tid & 31;
    const int wm   = warp & 1;
    const int wn   = warp >> 1;
    const int grp  = lane >> 2;
    const int tig  = lane & 3;

#pragma unroll
    for (int mf = 0; mf < 4; mf++) {
        const int r0 = m0 + wm * 64 + mf * 16 + grp;
#pragma unroll
        for (int nf = 0; nf < 4; nf++) {
            const int c0 = n0 + wn * 32 + nf * 8 + tig * 2;
            const float* d = acc[mf][nf];
#pragma unroll
            for (int half = 0; half < 2; half++) {
                const int m = r0 + half * 8;
                float2 o = make_float2(d[half * 2], d[half * 2 + 1]);
                o.x += bias[c0]; o.y += bias[c0 + 1];
                *(float2*)(C + (size_t)m * DIM_ + c0) = o;
            }
        }
    }
}

__global__ void k_fill_mem(const float* __restrict__ mk, const float* __restrict__ mv)
{
    int idx = blockIdx.x * blockDim.x + threadIdx.x;      // B*H*M*DH elems
    int d = idx & 63;
    int r = idx >> 6;
    int j  = r % MM_;  r /= MM_;
    int h  = r % H_;
    int b  = r / H_;
    size_t dst = (((size_t)(b * H_ + h)) * J_ + j) * DH_ + d;
    size_t src = ((size_t)h * MM_ + j) * DH_ + d;
    g_k[dst] = mk[src];
    g_v[dst] = mv[src];
}

// ---------------- fused QK^T + head-mix via tf32x3 MMA, double-buffered ----------
__global__ void __launch_bounds__(256, 2) k_dots_mix(const float* __restrict__ pre)
{
    const int b  = blockIdx.z;
    const int i0 = blockIdx.y * 32;
    const int j0 = blockIdx.x * 32;
    if (j0 > i0 + 31 + MM_) return;     // fully above causal band

    __shared__ __align__(16) float Qs[2][32][68];
    __shared__ __align__(16) float Ks[2][32][68];
    __shared__ float Ppre[H_ * H_];

    const int tid  = threadIdx.x;
    const int warp = tid >> 5;
    const int lane = tid & 31;
    const int wi   = warp & 1;
    const int wj   = warp >> 1;
    const int grp  = lane >> 2;
    const int tig  = lane & 3;

    Ppre[tid] = pre[tid];

    const int lr = tid >> 3;
    const int lc = (tid & 7) << 2;
    const int jrow = j0 + lr;
    const bool jvalid = jrow < J_;

    const int ri = wi * 16 + grp;
    const int rj = wj * 8 + grp;

    float acc[H_][4];
#pragma unroll
    for (int ko = 0; ko < H_; ko++)
#pragma unroll
        for (int e = 0; e < 4; e++) acc[ko][e] = 0.f;

    const float* qbase = g_q + ((size_t)b * H_ * N_ + (size_t)(i0 + lr)) * DH_;
    const float* kbase = g_k + ((size_t)b * H_ * J_ + (size_t)jrow) * DH_;
    const size_t qstep = (size_t)N_ * DH_;      // per-head stride
    const size_t kstep = (size_t)J_ * DH_;

    float4 q0r = *(const float4*)(qbase + lc);
    float4 q1r = *(const float4*)(qbase + lc + 32);
    float4 k0r, k1r;
    if (jvalid) {
        k0r = *(const float4*)(kbase + lc);
        k1r = *(const float4*)(kbase + lc + 32);
    } else {
        k0r = make_float4(0.f, 0.f, 0.f, 0.f);
        k1r = k0r;
    }
    *(float4*)&Qs[0][lr][lc]      = q0r;
    *(float4*)&Qs[0][lr][lc + 32] = q1r;
    *(float4*)&Ks[0][lr][lc]      = k0r;
    *(float4*)&Ks[0][lr][lc + 32] = k1r;

#pragma unroll 1
    for (int h = 0; h < H_; h++) {
        const int cb = h & 1;
        if (h + 1 < H_) {
            const float* qn = qbase + (size_t)(h + 1) * qstep;
            q0r = *(const float4*)(qn + lc);
            q1r = *(const float4*)(qn + lc + 32);
            if (jvalid) {
                const float* kn = kbase + (size_t)(h + 1) * kstep;
                k0r = *(const float4*)(kn + lc);
                k1r = *(const float4*)(kn + lc + 32);
            }
        }
        __syncthreads();

        float s0 = 0.f, s1 = 0.f, s2 = 0.f, s3 = 0.f;
#pragma unroll
        for (int k0 = 0; k0 < DH_; k0 += 8) {
            const float a0f = Qs[cb][ri]    [k0 + tig];
            const float a1f = Qs[cb][ri + 8][k0 + tig];
            const float a2f = Qs[cb][ri]    [k0 + tig + 4];
            const float a3f = Qs[cb][ri + 8][k0 + tig + 4];
            const float b0f = Ks[cb][rj][k0 + tig];
            const float b1f = Ks[cb][rj][k0 + tig + 4];

            const unsigned a0h = to_tf32(a0f), a1h = to_tf32(a1f);
            const unsigned a2h = to_tf32(a2f), a3h = to_tf32(a3f);
            const unsigned b0h = to_tf32(b0f), b1h = to_tf32(b1f);
            const unsigned a0l = to_tf32(a0f - __uint_as_float(a0h));
            const unsigned a1l = to_tf32(a1f - __uint_as_float(a1h));
            const unsigned a2l = to_tf32(a2f - __uint_as_float(a2h));
            const unsigned a3l = to_tf32(a3f - __uint_as_float(a3h));
            const unsigned b0l = to_tf32(b0f - __uint_as_float(b0h));
            const unsigned b1l = to_tf32(b1f - __uint_as_float(b1h));

            mma_tf32(s0, s1, s2, s3, a0h, a1h, a2h, a3h, b0h, b1h);   // hi*hi
            mma_tf32(s0, s1, s2, s3, a0l, a1l, a2l, a3l, b0h, b1h);   // lo*hi
            mma_tf32(s0, s1, s2, s3, a0h, a1h, a2h, a3h, b0l, b1l);   // hi*lo
        }

#pragma unroll
        for (int ko = 0; ko < H_; ko++) {
            const float p = Ppre[h * H_ + ko] * SCALE_;
            acc[ko][0] += p * s0; acc[ko][1] += p * s1;
            acc[ko][2] += p * s2; acc[ko][3] += p * s3;
        }

        if (h + 1 < H_) {
            const int nb = cb ^ 1;
            *(float4*)&Qs[nb][lr][lc]      = q0r;
            *(float4*)&Qs[nb][lr][lc + 32] = q1r;
            *(float4*)&Ks[nb][lr][lc]      = k0r;
            *(float4*)&Ks[nb][lr][lc + 32] = k1r;
        }
    }

    const int gi = i0 + ri;
    const int gj = j0 + wj * 8 + tig * 2;
#pragma unroll
    for (int ko = 0; ko < H_; ko++) {
        const size_t base = (((size_t)(b * H_ + ko)) * N_ + gi) * J_ + gj;
        if (gj < J_) {
            g_smix[base]              = acc[ko][0];
            g_smix[base + 8 * J_]     = acc[ko][2];
        }
        if (gj + 1 < J_) {
            g_smix[base + 1]          = acc[ko][1];
            g_smix[base + 8 * J_ + 1] = acc[ko][3];
        }
    }
}

// ---------------- per-row top-k + softmax + sparse A*V (vectorized sweeps) -------
__device__ __forceinline__ unsigned fkey(float f)
{
    unsigned u = __float_as_uint(f);
    return (u & 0x80000000u) ? ~u : (u | 0x80000000u);
}
__device__ __forceinline__ float finv(unsigned k)
{
    return (k & 0x80000000u) ? __uint_as_float(k ^ 0x80000000u)
                             : __uint_as_float(~k);
}

// single-warp suffix-scan over 256 bins; finds bin B with suffix(B) >= kth > suffix(B+1)
__device__ __forceinline__ void scan_bins(const int* hist, int kth, int tid,
                                          int* s_bin, int* s_above)
{
    if (tid < 32) {
        int loc[8];
        int sum = 0;
#pragma unroll
        for (int e = 0; e < 8; e++) { loc[e] = hist[tid * 8 + e]; sum += loc[e]; }
        int v = sum;
#pragma unroll
        for (int o = 1; o < 32; o <<= 1) {
            const int u = __shfl_down_sync(0xffffffffu, v, o);
            if (tid + o < 32) v += u;
        }
        const int after_lane = v - sum;        // count in lanes > tid
        int run = after_lane;
        int sfx[8];
#pragma unroll
        for (int e = 7; e >= 0; e--) { run += loc[e]; sfx[e] = run; }
#pragma unroll
        for (int e = 0; e < 8; e++) {
            const int above = (e == 7) ? after_lane : sfx[e + 1];
            if (sfx[e] >= kth && above < kth) { *s_bin = tid * 8 + e; *s_above = above; }
        }
    }
}

__global__ void __launch_bounds__(256) k_topk_av()
{
    const int i  = blockIdx.x;
    const int ko = blockIdx.y;
    const int b  = blockIdx.z;
    const int tid = threadIdx.x;
    const int lane = tid & 31;
    const int jmax = min(J_, i + MM_ + 1);

    __shared__ __align__(16) unsigned skeys[J_];
    __shared__ int   sidx[J_];       // survivor indices; reused as candB
    __shared__ float swgt[J_];       // survivor weights; reused as candA
    __shared__ int   hist[256];
    __shared__ unsigned redk[8];
    __shared__ float redf[8];
    __shared__ unsigned s_maxk, s_tkey;
    __shared__ float s_sum;
    __shared__ int   s_bin, s_above, s_cnt;
    __shared__ float accb[4][64];

    const float* row = g_smix + (((size_t)(b * H_ + ko)) * N_ + i) * J_;

    // --- sweep 1 (vectorized x4): load keys + top-byte histogram ----------------
    hist[tid] = 0;
    __syncthreads();
    unsigned lmax = 0u;
    const int nIterV = (jmax + 1023) >> 10;         // uniform across block
    for (int it = 0; it < nIterV; it++) {
        const int base = (tid << 2) + (it << 10);   // multiple of 4, < J_ when any valid
        unsigned k4[4];
        if (base < jmax) {                           // safe: row has J_ elems, J_%4==0
            const float4 v4 = *(const float4*)(row + base);
            k4[0] = fkey(v4.x); k4[1] = fkey(v4.y);
            k4[2] = fkey(v4.z); k4[3] = fkey(v4.w);
            *(uint4*)&skeys[base] = make_uint4(k4[0], k4[1], k4[2], k4[3]);
        } else {
            k4[0] = k4[1] = k4[2] = k4[3] = 0u;
        }
#pragma unroll
        for (int e = 0; e < 4; e++) {
            const bool valid = (base + e) < jmax;
            if (valid) lmax = max(lmax, k4[e]);
            const unsigned bin = valid ? (k4[e] >> 24) : 300u;
            const unsigned mmask = __match_any_sync(0xffffffffu, bin);
            if (valid && (mmask & ((1u << lane) - 1u)) == 0u)
                atomicAdd(&hist[bin], __popc(mmask));
        }
    }
#pragma unroll
    for (int o = 16; o > 0; o >>= 1) lmax = max(lmax, __shfl_xor_sync(0xffffffffu, lmax, o));
    if (lane == 0) redk[tid >> 5] = lmax;
    __syncthreads();
    if (tid == 0) {
        unsigned m = redk[0];
#pragma unroll
        for (int w = 1; w < 8; w++) m = max(m, redk[w]);
        s_maxk = m;
    }
    __syncthreads();
    const float vmax = finv(s_maxk);

    // --- exact K-th largest key: bin scan + boundary-bin candidate select -------
    unsigned tkey = 0u;
    if (jmax > KTOP_) {
        scan_bins(hist, KTOP_, tid, &s_bin, &s_above);
        __syncthreads();
        const int b0 = s_bin;
        int kth = KTOP_ - s_above;

        if (tid == 0) s_cnt = 0;
        __syncthreads();
        unsigned* candA = (unsigned*)swgt;
        unsigned* candB = (unsigned*)sidx;
        // sweep 2 (vectorized x4): scatter boundary-bin candidates
        for (int it = 0; it < nIterV; it++) {
            const int base = (tid << 2) + (it << 10);
            if (base < jmax) {
                const uint4 k4 = *(const uint4*)&skeys[base];
                const unsigned ks[4] = {k4.x, k4.y, k4.z, k4.w};
#pragma unroll
                for (int e = 0; e < 4; e++)
                    if ((base + e) < jmax && (ks[e] >> 24) == (unsigned)b0)
                        candA[atomicAdd(&s_cnt, 1)] = ks[e];
            }
        }
        __syncthreads();
        int c = s_cnt;
        unsigned* cur = candA;
        unsigned* alt = candB;
        int shift = 16;
        while (c > 48 && shift >= 0) {
            hist[tid] = 0;
            __syncthreads();
            for (int t = tid; t < c; t += 256)
                atomicAdd(&hist[(cur[t] >> shift) & 255u], 1);
            __syncthreads();
            scan_bins(hist, kth, tid, &s_bin, &s_above);
            __syncthreads();
            const int bsel = s_bin;
            kth -= s_above;
            if (tid == 0) s_cnt = 0;
            __syncthreads();
            for (int t = tid; t < c; t += 256)
                if (((cur[t] >> shift) & 255u) == (unsigned)bsel)
                    alt[atomicAdd(&s_cnt, 1)] = cur[t];
            __syncthreads();
            c = s_cnt;
            unsigned* tmp = cur; cur = alt; alt = tmp;
            shift -= 8;
        }
        if (shift < 0) {
            if (tid == 0) s_tkey = cur[0];          // all remaining keys identical
        } else {
            // exact rank-count select among c (<=48) candidates
            for (int t = tid; t < c; t += 256) {
                const unsigned x = cur[t];
                int gt = 0, ge = 0;
                for (int u = 0; u < c; u++) { gt += (cur[u] > x); ge += (cur[u] >= x); }
                if (gt < kth && ge >= kth) s_tkey = x;
            }
        }
        __syncthreads();
        tkey = s_tkey;
    }

    // --- sweep 3 (vectorized x4): compact survivors + exp-sum -------------------
    if (tid == 0) s_cnt = 0;
    __syncthreads();
    float lsum = 0.f;
    for (int it = 0; it < nIterV; it++) {
        const int base = (tid << 2) + (it << 10);
        if (base < jmax) {
            const uint4 k4 = *(const uint4*)&skeys[base];
            const unsigned ks[4] = {k4.x, k4.y, k4.z, k4.w};
#pragma unroll
            for (int e = 0; e < 4; e++) {
                if ((base + e) < jmax && ks[e] >= tkey) {
                    const float w = __expf(finv(ks[e]) - vmax);
                    lsum += w;
                    const int p = atomicAdd(&s_cnt, 1);
                    sidx[p] = base + e;
                    swgt[p] = w;
                }
            }
        }
    }
#pragma unroll
    for (int o = 16; o > 0; o >>= 1) lsum += __shfl_xor_sync(0xffffffffu, lsum, o);
    if (lane == 0) redf[tid >> 5] = lsum;
    __syncthreads();
    if (tid == 0) {
        float t = 0.f;
#pragma unroll
        for (int w = 0; w < 8; w++) t += redf[w];
        s_sum = t;
    }
    __syncthreads();
    const float sumexp = s_sum;
    const int nsurv = s_cnt;

    // --- gather-weighted sum over surviving v rows ------------------------------
    const int d = tid & 63;
    const int g = tid >> 6;
    float acc = 0.f;
    const float* vb = g_v + ((size_t)(b * H_ + ko)) * J_ * DH_ + d;
    for (int s = g; s < nsurv; s += 4)
        acc += swgt[s] * vb[(size_t)sidx[s] * DH_];
    accb[g][d] = acc;
    __syncthreads();
    if (g == 0) {
        const float tot = accb[0][d] + accb[1][d] + accb[2][d] + accb[3][d];
        g_att[((size_t)(b * N_ + i)) * DIM_ + ko * DH_ + d] = tot / sumexp;
    }
}

// ---------------- launch ---------------------------------------------------------
extern "C" void kernel_launch(void* const* d_in, const int* in_sizes, int n_in,
                              void* d_out, int out_size)
{
    (void)in_sizes; (void)n_in; (void)out_size;
    const float* x    = (const float*)d_in[0];
    const float* Wq   = (const float*)d_in[1];
    const float* Wkv  = (const float*)d_in[2];
    const float* Wo   = (const float*)d_in[3];
    const float* bo   = (const float*)d_in[4];
    const float* pre  = (const float*)d_in[5];
    const float* memk = (const float*)d_in[7];
    const float* memv = (const float*)d_in[8];
    float* out = (float*)d_out;

    k_gemm_qkv<<<dim3(3 * DIM_ / 128, (B_ * N_) / 128), 256>>>(x, Wq, Wkv);
    k_fill_mem<<<(B_ * H_ * MM_ * DH_) / 256, 256>>>(memk, memv);
    k_dots_mix<<<dim3((J_ + 31) / 32, N_ / 32, B_), 256>>>(pre);
    k_topk_av<<<dim3(N_, H_, B_), 256>>>();
    k_gemm_o<<<dim3(DIM_ / 128, (B_ * N_) / 128), 256>>>(Wo, bo, out);
}

// round 16
// speedup vs baseline: 1.2417x; 1.0015x over previous
#include <cuda_runtime.h>
#include <cstdint>
#include <cstddef>

#define B_    2
#define N_    2048
#define DIM_  1024
#define H_    16
#define DH_   64
#define MM_   16
#define J_    2064          // N_ + MM_
#define KTOP_ 64
#define SCALE_ 0.125f

// ---------------- static device scratch ----------------
__device__ float g_q   [(size_t)B_*H_*N_*DH_];      // (b,h,i,d)
__device__ float g_k   [(size_t)B_*H_*J_*DH_];      // (b,h,j,d), j<M = mem
__device__ float g_v   [(size_t)B_*H_*J_*DH_];
__device__ float g_smix[(size_t)B_*H_*N_*J_];       // mixed scores (b,k,i,j)
__device__ float g_att [(size_t)B_*N_*DIM_];        // attention output (b,i,k*64+d)

// ---------------- tf32 MMA helpers -----------------------------------------------
__device__ __forceinline__ unsigned to_tf32(float x)
{
    unsigned r;
    asm("cvt.rna.tf32.f32 %0, %1;" : "=r"(r) : "f"(x));
    return r;
}

__device__ __forceinline__ void mma_tf32(float& d0, float& d1, float& d2, float& d3,
                                         unsigned a0, unsigned a1, unsigned a2, unsigned a3,
                                         unsigned b0, unsigned b1)
{
    asm volatile("mma.sync.aligned.m16n8k8.row.col.f32.tf32.tf32.f32 "
                 "{%0,%1,%2,%3}, {%4,%5,%6,%7}, {%8,%9}, {%0,%1,%2,%3};\n"
                 : "+f"(d0), "+f"(d1), "+f"(d2), "+f"(d3)
                 : "r"(a0), "r"(a1), "r"(a2), "r"(a3), "r"(b0), "r"(b1));
}

__device__ __forceinline__ unsigned smem_u32(const void* p)
{
    return (unsigned)__cvta_generic_to_shared(p);
}
#define CP16(dst, src) asm volatile("cp.async.cg.shared.global [%0], [%1], 16;" :: "r"(dst), "l"(src))
#define CP_COMMIT()    asm volatile("cp.async.commit_group;")
#define CP_WAIT2()     asm volatile("cp.async.wait_group 2;")

// ======= 128x128 / BK=16 tf32x3 GEMM, 3-stage cp.async smem pipeline =============
struct GemmSmem3 {
    float As[3][128][20];   // [stage][m][k]  banks: 20*grp+tig -> conflict-free
    float Bs[3][16][136];   // [stage][k][n]  banks: 8*tig+grp  -> conflict-free
};
#define GEMM_SMEM3_BYTES ((int)sizeof(GemmSmem3))   // 56832

__device__ __forceinline__ void gemm_tiles(GemmSmem3& S,
                                           const float* __restrict__ Aeff,
                                           const float* __restrict__ Bm,
                                           int Ndim, int Kdim,
                                           int m0, int n0,
                                           float acc[4][4][4])
{
    const int tid  = threadIdx.x;
    const int warp = tid >> 5;
    const int lane = tid & 31;
    const int wm   = warp & 1;
    const int wn   = warp >> 1;
    const int grp  = lane >> 2;
    const int tig  = lane & 3;

    const int arow  = tid >> 1;          // 0..127
    const int acol8 = (tid & 1) * 8;     // 0 or 8
    const int brow  = tid >> 4;          // 0..15
    const int bcol8 = (tid & 15) * 8;    // 0..120

    const float* ag = Aeff + (size_t)(m0 + arow) * Kdim + acol8;
    const float* bg = Bm + n0 + bcol8;

    unsigned a_dst[3], b_dst[3];
#pragma unroll
    for (int st = 0; st < 3; st++) {
        a_dst[st] = smem_u32(&S.As[st][arow][acol8]);
        b_dst[st] = smem_u32(&S.Bs[st][brow][bcol8]);
    }

    const int nslabs = Kdim >> 4;        // >= 2 always here

    // prologue: stages 0 and 1
#pragma unroll
    for (int st = 0; st < 2; st++) {
        const int k0 = st * 16;
        CP16(a_dst[st],      ag + k0);
        CP16(a_dst[st] + 16, ag + k0 + 4);
        CP16(b_dst[st],      bg + (size_t)(k0 + brow) * Ndim);
        CP16(b_dst[st] + 16, bg + (size_t)(k0 + brow) * Ndim + 4);
        CP_COMMIT();
    }

    int s = 0;
    for (int t = 0; t < nslabs; t++) {
        if (t + 2 < nslabs) {
            const int ns = (s + 2 >= 3) ? s - 1 : s + 2;   // (t+2)%3
            const int k0 = (t + 2) << 4;
            CP16(a_dst[ns],      ag + k0);
            CP16(a_dst[ns] + 16, ag + k0 + 4);
            CP16(b_dst[ns],      bg + (size_t)(k0 + brow) * Ndim);
            CP16(b_dst[ns] + 16, bg + (size_t)(k0 + brow) * Ndim + 4);
        }
        CP_COMMIT();            // empty group near the tail keeps count uniform
        CP_WAIT2();             // slab t guaranteed resident
        __syncthreads();

#pragma unroll
        for (int ks = 0; ks < 2; ks++) {
            const int kk = ks * 8 + tig;
            unsigned ah[4][4], al[4][4], bh[4][2], bl[4][2];
#pragma unroll
            for (int nf = 0; nf < 4; nf++) {
                const int col = wn * 32 + nf * 8 + grp;
                const float b0f = S.Bs[s][kk][col];
                const float b1f = S.Bs[s][kk + 4][col];
                bh[nf][0] = to_tf32(b0f);
                bh[nf][1] = to_tf32(b1f);
                bl[nf][0] = to_tf32(b0f - __uint_as_float(bh[nf][0]));
                bl[nf][1] = to_tf32(b1f - __uint_as_float(bh[nf][1]));
            }
#pragma unroll
            for (int mf = 0; mf < 4; mf++) {
                const int row = wm * 64 + mf * 16 + grp;
                const float a0f = S.As[s][row][kk];
                const float a1f = S.As[s][row + 8][kk];
                const float a2f = S.As[s][row][kk + 4];
                const float a3f = S.As[s][row + 8][kk + 4];
                ah[mf][0] = to_tf32(a0f); ah[mf][1] = to_tf32(a1f);
                ah[mf][2] = to_tf32(a2f); ah[mf][3] = to_tf32(a3f);
                al[mf][0] = to_tf32(a0f - __uint_as_float(ah[mf][0]));
                al[mf][1] = to_tf32(a1f - __uint_as_float(ah[mf][1]));
                al[mf][2] = to_tf32(a2f - __uint_as_float(ah[mf][2]));
                al[mf][3] = to_tf32(a3f - __uint_as_float(ah[mf][3]));
            }
#pragma unroll
            for (int mf = 0; mf < 4; mf++)
#pragma unroll
                for (int nf = 0; nf < 4; nf++) {
                    float* d = acc[mf][nf];
                    mma_tf32(d[0], d[1], d[2], d[3],
                             ah[mf][0], ah[mf][1], ah[mf][2], ah[mf][3],
                             bh[nf][0], bh[nf][1]);
                    mma_tf32(d[0], d[1], d[2], d[3],
                             al[mf][0], al[mf][1], al[mf][2], al[mf][3],
                             bh[nf][0], bh[nf][1]);
                    mma_tf32(d[0], d[1], d[2], d[3],
                             ah[mf][0], ah[mf][1], ah[mf][2], ah[mf][3],
                             bl[nf][0], bl[nf][1]);
                }
        }
        __syncthreads();
        s = (s + 1 >= 3) ? 0 : s + 1;
    }
}

// ---- merged Q/KV projection + mem_k/mem_v fill ----------------------------------
// grid = (25, 32): tiles x=0..23 = [Wq | Wkv] columns; x=24 = mem fill
// (32 CTAs x 1024 elems = 32768 = B*H*M*DH).
__global__ void __launch_bounds__(256) k_gemm_qkv(const float* __restrict__ x,
                                                  const float* __restrict__ Wq,
                                                  const float* __restrict__ Wkv,
                                                  const float* __restrict__ mk,
                                                  const float* __restrict__ mv)
{
    extern __shared__ char smem_raw[];
    GemmSmem3& S = *reinterpret_cast<GemmSmem3*>(smem_raw);

    if (blockIdx.x == 24) {
        // mem fill: 32 CTAs (blockIdx.y = 0..31) x 1024 elems each; total 32768
        const int slice = blockIdx.y;
        for (int t = threadIdx.x; t < 1024; t += 256) {
            const int idx = slice * 1024 + t;       // < 32768 = B_*H_*MM_*DH_
            const int d = idx & 63;
            int r = idx >> 6;                       // 0..511
            const int j = r % MM_;  r /= MM_;       // r -> 0..31
            const int h = r % H_;
            const int b = r / H_;                   // 0..1
            const size_t dst = (((size_t)(b * H_ + h)) * J_ + j) * DH_ + d;
            const size_t src = ((size_t)h * MM_ + j) * DH_ + d;
            g_k[dst] = mk[src];
            g_v[dst] = mv[src];
        }
        return;
    }

    const int n0g = blockIdx.x * 128;        // 0..3071
    const int m0  = blockIdx.y * 128;
    const bool isQ = n0g < DIM_;
    const float* Bm = isQ ? Wq : Wkv;
    const int Ndim  = isQ ? DIM_ : 2 * DIM_;
    const int n0    = isQ ? n0g : n0g - DIM_;

    float acc[4][4][4];
#pragma unroll
    for (int mf = 0; mf < 4; mf++)
#pragma unroll
        for (int nf = 0; nf < 4; nf++)
#pragma unroll
            for (int e = 0; e < 4; e++) acc[mf][nf][e] = 0.f;

    gemm_tiles(S, x, Bm, Ndim, DIM_, m0, n0, acc);

    const int tid  = threadIdx.x;
    const int warp = tid >> 5;
    const int lane = tid & 31;
    const int wm   = warp & 1;
    const int wn   = warp >> 1;
    const int grp  = lane >> 2;
    const int tig  = lane & 3;

#pragma unroll
    for (int mf = 0; mf < 4; mf++) {
        const int r0 = m0 + wm * 64 + mf * 16 + grp;
#pragma unroll
        for (int nf = 0; nf < 4; nf++) {
            const int c0 = n0 + wn * 32 + nf * 8 + tig * 2;
            const float* d = acc[mf][nf];
#pragma unroll
            for (int half = 0; half < 2; half++) {
                const int m = r0 + half * 8;
                const float2 o = make_float2(d[half * 2], d[half * 2 + 1]);
                const int b = m >> 11;
                const int i = m & (N_ - 1);
                if (isQ) {
                    const int h = c0 >> 6, dd = c0 & 63;
                    *(float2*)(g_q + (((size_t)(b * H_ + h)) * N_ + i) * DH_ + dd) = o;
                } else if (c0 < DIM_) {
                    const int h = c0 >> 6, dd = c0 & 63;
                    *(float2*)(g_k + (((size_t)(b * H_ + h)) * J_ + MM_ + i) * DH_ + dd) = o;
                } else {
                    const int c = c0 - DIM_;
                    const int h = c >> 6, dd = c & 63;
                    *(float2*)(g_v + (((size_t)(b * H_ + h)) * J_ + MM_ + i) * DH_ + dd) = o;
                }
            }
        }
    }
}

// ---- output projection: C = g_att @ Wo + bo -------------------------------------
__global__ void __launch_bounds__(256) k_gemm_o(const float* __restrict__ Wo,
                                                const float* __restrict__ bias,
                                                float* __restrict__ C)
{
    extern __shared__ char smem_raw[];
    GemmSmem3& S = *reinterpret_cast<GemmSmem3*>(smem_raw);

    const int m0 = blockIdx.y * 128;
    const int n0 = blockIdx.x * 128;

    float acc[4][4][4];
#pragma unroll
    for (int mf = 0; mf < 4; mf++)
#pragma unroll
        for (int nf = 0; nf < 4; nf++)
#pragma unroll
            for (int e = 0; e < 4; e++) acc[mf][nf][e] = 0.f;

    gemm_tiles(S, g_att, Wo, DIM_, DIM_, m0, n0, acc);

    const int tid  = threadIdx.x;
    const int warp = tid >> 5;
    const int lane = tid & 31;
    const int wm   = warp & 1;
    const int wn   = warp >> 1;
    const int grp  = lane >> 2;
    const int tig  = lane & 3;

#pragma unroll
    for (int mf = 0; mf < 4; mf++) {
        const int r0 = m0 + wm * 64 + mf * 16 + grp;
#pragma unroll
        for (int nf = 0; nf < 4; nf++) {
            const int c0 = n0 + wn * 32 + nf * 8 + tig * 2;
            const float* d = acc[mf][nf];
#pragma unroll
            for (int half = 0; half < 2; half++) {
                const int m = r0 + half * 8;
                float2 o = make_float2(d[half * 2], d[half * 2 + 1]);
                o.x += bias[c0]; o.y += bias[c0 + 1];
                *(float2*)(C + (size_t)m * DIM_ + c0) = o;
            }
        }
    }
}

// ---------------- fused QK^T + head-mix via tf32x3 MMA, double-buffered ----------
__global__ void __launch_bounds__(256, 2) k_dots_mix(const float* __restrict__ pre)
{
    const int b  = blockIdx.z;
    const int i0 = blockIdx.y * 32;
    const int j0 = blockIdx.x * 32;
    if (j0 > i0 + 31 + MM_) return;     // fully above causal band

    __shared__ __align__(16) float Qs[2][32][68];
    __shared__ __align__(16) float Ks[2][32][68];
    __shared__ float Ppre[H_ * H_];

    const int tid  = threadIdx.x;
    const int warp = tid >> 5;
    const int lane = tid & 31;
    const int wi   = warp & 1;
    const int wj   = warp >> 1;
    const int grp  = lane >> 2;
    const int tig  = lane & 3;

    Ppre[tid] = pre[tid];

    const int lr = tid >> 3;
    const int lc = (tid & 7) << 2;
    const int jrow = j0 + lr;
    const bool jvalid = jrow < J_;

    const int ri = wi * 16 + grp;
    const int rj = wj * 8 + grp;

    float acc[H_][4];
#pragma unroll
    for (int ko = 0; ko < H_; ko++)
#pragma unroll
        for (int e = 0; e < 4; e++) acc[ko][e] = 0.f;

    const float* qbase = g_q + ((size_t)b * H_ * N_ + (size_t)(i0 + lr)) * DH_;
    const float* kbase = g_k + ((size_t)b * H_ * J_ + (size_t)jrow) * DH_;
    const size_t qstep = (size_t)N_ * DH_;      // per-head stride
    const size_t kstep = (size_t)J_ * DH_;

    float4 q0r = *(const float4*)(qbase + lc);
    float4 q1r = *(const float4*)(qbase + lc + 32);
    float4 k0r, k1r;
    if (jvalid) {
        k0r = *(const float4*)(kbase + lc);
        k1r = *(const float4*)(kbase + lc + 32);
    } else {
        k0r = make_float4(0.f, 0.f, 0.f, 0.f);
        k1r = k0r;
    }
    *(float4*)&Qs[0][lr][lc]      = q0r;
    *(float4*)&Qs[0][lr][lc + 32] = q1r;
    *(float4*)&Ks[0][lr][lc]      = k0r;
    *(float4*)&Ks[0][lr][lc + 32] = k1r;

#pragma unroll 1
    for (int h = 0; h < H_; h++) {
        const int cb = h & 1;
        if (h + 1 < H_) {
            const float* qn = qbase + (size_t)(h + 1) * qstep;
            q0r = *(const float4*)(qn + lc);
            q1r = *(const float4*)(qn + lc + 32);
            if (jvalid) {
                const float* kn = kbase + (size_t)(h + 1) * kstep;
                k0r = *(const float4*)(kn + lc);
                k1r = *(const float4*)(kn + lc + 32);
            }
        }
        __syncthreads();

        float s0 = 0.f, s1 = 0.f, s2 = 0.f, s3 = 0.f;
#pragma unroll
        for (int k0 = 0; k0 < DH_; k0 += 8) {
            const float a0f = Qs[cb][ri]    [k0 + tig];
            const float a1f = Qs[cb][ri + 8][k0 + tig];
            const float a2f = Qs[cb][ri]    [k0 + tig + 4];
            const float a3f = Qs[cb][ri + 8][k0 + tig + 4];
            const float b0f = Ks[cb][rj][k0 + tig];
            const float b1f = Ks[cb][rj][k0 + tig + 4];

            const unsigned a0h = to_tf32(a0f), a1h = to_tf32(a1f);
            const unsigned a2h = to_tf32(a2f), a3h = to_tf32(a3f);
            const unsigned b0h = to_tf32(b0f), b1h = to_tf32(b1f);
            const unsigned a0l = to_tf32(a0f - __uint_as_float(a0h));
            const unsigned a1l = to_tf32(a1f - __uint_as_float(a1h));
            const unsigned a2l = to_tf32(a2f - __uint_as_float(a2h));
            const unsigned a3l = to_tf32(a3f - __uint_as_float(a3h));
            const unsigned b0l = to_tf32(b0f - __uint_as_float(b0h));
            const unsigned b1l = to_tf32(b1f - __uint_as_float(b1h));

            mma_tf32(s0, s1, s2, s3, a0h, a1h, a2h, a3h, b0h, b1h);   // hi*hi
            mma_tf32(s0, s1, s2, s3, a0l, a1l, a2l, a3l, b0h, b1h);   // lo*hi
            mma_tf32(s0, s1, s2, s3, a0h, a1h, a2h, a3h, b0l, b1l);   // hi*lo
        }

#pragma unroll
        for (int ko = 0; ko < H_; ko++) {
            const float p = Ppre[h * H_ + ko] * SCALE_;
            acc[ko][0] += p * s0; acc[ko][1] += p * s1;
            acc[ko][2] += p * s2; acc[ko][3] += p * s3;
        }

        if (h + 1 < H_) {
            const int nb = cb ^ 1;
            *(float4*)&Qs[nb][lr][lc]      = q0r;
            *(float4*)&Qs[nb][lr][lc + 32] = q1r;
            *(float4*)&Ks[nb][lr][lc]      = k0r;
            *(float4*)&Ks[nb][lr][lc + 32] = k1r;
        }
    }

    const int gi = i0 + ri;
    const int gj = j0 + wj * 8 + tig * 2;
#pragma unroll
    for (int ko = 0; ko < H_; ko++) {
        const size_t base = (((size_t)(b * H_ + ko)) * N_ + gi) * J_ + gj;
        if (gj < J_) {
            g_smix[base]              = acc[ko][0];
            g_smix[base + 8 * J_]     = acc[ko][2];
        }
        if (gj + 1 < J_) {
            g_smix[base + 1]          = acc[ko][1];
            g_smix[base + 8 * J_ + 1] = acc[ko][3];
        }
    }
}

// ---------------- per-row top-k + softmax + sparse A*V (vectorized sweeps) -------
__device__ __forceinline__ unsigned fkey(float f)
{
    unsigned u = __float_as_uint(f);
    return (u & 0x80000000u) ? ~u : (u | 0x80000000u);
}
__device__ __forceinline__ float finv(unsigned k)
{
    return (k & 0x80000000u) ? __uint_as_float(k ^ 0x80000000u)
                             : __uint_as_float(~k);
}

// single-warp suffix-scan over 256 bins; finds bin B with suffix(B) >= kth > suffix(B+1)
__device__ __forceinline__ void scan_bins(const int* hist, int kth, int tid,
                                          int* s_bin, int* s_above)
{
    if (tid < 32) {
        int loc[8];
        int sum = 0;
#pragma unroll
        for (int e = 0; e < 8; e++) { loc[e] = hist[tid * 8 + e]; sum += loc[e]; }
        int v = sum;
#pragma unroll
        for (int o = 1; o < 32; o <<= 1) {
            const int u = __shfl_down_sync(0xffffffffu, v, o);
            if (tid + o < 32) v += u;
        }
        const int after_lane = v - sum;        // count in lanes > tid
        int run = after_lane;
        int sfx[8];
#pragma unroll
        for (int e = 7; e >= 0; e--) { run += loc[e]; sfx[e] = run; }
#pragma unroll
        for (int e = 0; e < 8; e++) {
            const int above = (e == 7) ? after_lane : sfx[e + 1];
            if (sfx[e] >= kth && above < kth) { *s_bin = tid * 8 + e; *s_above = above; }
        }
    }
}

__global__ void __launch_bounds__(256) k_topk_av()
{
    const int i  = blockIdx.x;
    const int ko = blockIdx.y;
    const int b  = blockIdx.z;
    const int tid = threadIdx.x;
    const int lane = tid & 31;
    const int jmax = min(J_, i + MM_ + 1);

    __shared__ __align__(16) unsigned skeys[J_];
    __shared__ int   sidx[J_];       // survivor indices; reused as candB
    __shared__ float swgt[J_];       // survivor weights; reused as candA
    __shared__ int   hist[256];
    __shared__ unsigned redk[8];
    __shared__ float redf[8];
    __shared__ unsigned s_maxk, s_tkey;
    __shared__ float s_sum;
    __shared__ int   s_bin, s_above, s_cnt;
    __shared__ float accb[4][64];

    const float* row = g_smix + (((size_t)(b * H_ + ko)) * N_ + i) * J_;

    // --- sweep 1 (vectorized x4): load keys + top-byte histogram ----------------
    hist[tid] = 0;
    __syncthreads();
    unsigned lmax = 0u;
    const int nIterV = (jmax + 1023) >> 10;         // uniform across block
    for (int it = 0; it < nIterV; it++) {
        const int base = (tid << 2) + (it << 10);   // multiple of 4, < J_ when any valid
        unsigned k4[4];
        if (base < jmax) {                           // safe: row has J_ elems, J_%4==0
            const float4 v4 = *(const float4*)(row + base);
            k4[0] = fkey(v4.x); k4[1] = fkey(v4.y);
            k4[2] = fkey(v4.z); k4[3] = fkey(v4.w);
            *(uint4*)&skeys[base] = make_uint4(k4[0], k4[1], k4[2], k4[3]);
        } else {
            k4[0] = k4[1] = k4[2] = k4[3] = 0u;
        }
#pragma unroll
        for (int e = 0; e < 4; e++) {
            const bool valid = (base + e) < jmax;
            if (valid) lmax = max(lmax, k4[e]);
            const unsigned bin = valid ? (k4[e] >> 24) : 300u;
            const unsigned mmask = __match_any_sync(0xffffffffu, bin);
            if (valid && (mmask & ((1u << lane) - 1u)) == 0u)
                atomicAdd(&hist[bin], __popc(mmask));
        }
    }
#pragma unroll
    for (int o = 16; o > 0; o >>= 1) lmax = max(lmax, __shfl_xor_sync(0xffffffffu, lmax, o));
    if (lane == 0) redk[tid >> 5] = lmax;
    __syncthreads();
    if (tid == 0) {
        unsigned m = redk[0];
#pragma unroll
        for (int w = 1; w < 8; w++) m = max(m, redk[w]);
        s_maxk = m;
    }
    __syncthreads();
    const float vmax = finv(s_maxk);

    // --- exact K-th largest key: bin scan + boundary-bin candidate select -------
    unsigned tkey = 0u;
    if (jmax > KTOP_) {
        scan_bins(hist, KTOP_, tid, &s_bin, &s_above);
        __syncthreads();
        const int b0 = s_bin;
        int kth = KTOP_ - s_above;

        if (tid == 0) s_cnt = 0;
        __syncthreads();
        unsigned* candA = (unsigned*)swgt;
        unsigned* candB = (unsigned*)sidx;
        // sweep 2 (vectorized x4): scatter boundary-bin candidates
        for (int it = 0; it < nIterV; it++) {
            const int base = (tid << 2) + (it << 10);
            if (base < jmax) {
                const uint4 k4 = *(const uint4*)&skeys[base];
                const unsigned ks[4] = {k4.x, k4.y, k4.z, k4.w};
#pragma unroll
                for (int e = 0; e < 4; e++)
                    if ((base + e) < jmax && (ks[e] >> 24) == (unsigned)b0)
                        candA[atomicAdd(&s_cnt, 1)] = ks[e];
            }
        }
        __syncthreads();
        int c = s_cnt;
        unsigned* cur = candA;
        unsigned* alt = candB;
        int shift = 16;
        while (c > 48 && shift >= 0) {
            hist[tid] = 0;
            __syncthreads();
            for (int t = tid; t < c; t += 256)
                atomicAdd(&hist[(cur[t] >> shift) & 255u], 1);
            __syncthreads();
            scan_bins(hist, kth, tid, &s_bin, &s_above);
            __syncthreads();
            const int bsel = s_bin;
            kth -= s_above;
            if (tid == 0) s_cnt = 0;
            __syncthreads();
            for (int t = tid; t < c; t += 256)
                if (((cur[t] >> shift) & 255u) == (unsigned)bsel)
                    alt[atomicAdd(&s_cnt, 1)] = cur[t];
            __syncthreads();
            c = s_cnt;
            unsigned* tmp = cur; cur = alt; alt = tmp;
            shift -= 8;
        }
        if (shift < 0) {
            if (tid == 0) s_tkey = cur[0];          // all remaining keys identical
        } else {
            // exact rank-count select among c (<=48) candidates
            for (int t = tid; t < c; t += 256) {
                const unsigned x = cur[t];
                int gt = 0, ge = 0;
                for (int u = 0; u < c; u++) { gt += (cur[u] > x); ge += (cur[u] >= x); }
                if (gt < kth && ge >= kth) s_tkey = x;
            }
        }
        __syncthreads();
        tkey = s_tkey;
    }

    // --- sweep 3 (vectorized x4): compact survivors + exp-sum -------------------
    if (tid == 0) s_cnt = 0;
    __syncthreads();
    float lsum = 0.f;
    for (int it = 0; it < nIterV; it++) {
        const int base = (tid << 2) + (it << 10);
        if (base < jmax) {
            const uint4 k4 = *(const uint4*)&skeys[base];
            const unsigned ks[4] = {k4.x, k4.y, k4.z, k4.w};
#pragma unroll
            for (int e = 0; e < 4; e++) {
                if ((base + e) < jmax && ks[e] >= tkey) {
                    const float w = __expf(finv(ks[e]) - vmax);
                    lsum += w;
                    const int p = atomicAdd(&s_cnt, 1);
                    sidx[p] = base + e;
                    swgt[p] = w;
                }
            }
        }
    }
#pragma unroll
    for (int o = 16; o > 0; o >>= 1) lsum += __shfl_xor_sync(0xffffffffu, lsum, o);
    if (lane == 0) redf[tid >> 5] = lsum;
    __syncthreads();
    if (tid == 0) {
        float t = 0.f;
#pragma unroll
        for (int w = 0; w < 8; w++) t += redf[w];
        s_sum = t;
    }
    __syncthreads();
    const float sumexp = s_sum;
    const int nsurv = s_cnt;

    // --- gather-weighted sum over surviving v rows ------------------------------
    const int d = tid & 63;
    const int g = tid >> 6;
    float acc = 0.f;
    const float* vb = g_v + ((size_t)(b * H_ + ko)) * J_ * DH_ + d;
    for (int s = g; s < nsurv; s += 4)
        acc += swgt[s] * vb[(size_t)sidx[s] * DH_];
    accb[g][d] = acc;
    __syncthreads();
    if (g == 0) {
        const float tot = accb[0][d] + accb[1][d] + accb[2][d] + accb[3][d];
        g_att[((size_t)(b * N_ + i)) * DIM_ + ko * DH_ + d] = tot / sumexp;
    }
}

// ---------------- launch ---------------------------------------------------------
extern "C" void kernel_launch(void* const* d_in, const int* in_sizes, int n_in,
                              void* d_out, int out_size)
{
    (void)in_sizes; (void)n_in; (void)out_size;
    const float* x    = (const float*)d_in[0];
    const float* Wq   = (const float*)d_in[1];
    const float* Wkv  = (const float*)d_in[2];
    const float* Wo   = (const float*)d_in[3];
    const float* bo   = (const float*)d_in[4];
    const float* pre  = (const float*)d_in[5];
    const float* memk = (const float*)d_in[7];
    const float* memv = (const float*)d_in[8];
    float* out = (float*)d_out;

    cudaFuncSetAttribute(k_gemm_qkv, cudaFuncAttributeMaxDynamicSharedMemorySize, GEMM_SMEM3_BYTES);
    cudaFuncSetAttribute(k_gemm_o,   cudaFuncAttributeMaxDynamicSharedMemorySize, GEMM_SMEM3_BYTES);

    k_gemm_qkv<<<dim3(25, (B_ * N_) / 128), 256, GEMM_SMEM3_BYTES>>>(x, Wq, Wkv, memk, memv);
    k_dots_mix<<<dim3((J_ + 31) / 32, N_ / 32, B_), 256>>>(pre);
    k_topk_av<<<dim3(N_, H_, B_), 256>>>();
    k_gemm_o<<<dim3(DIM_ / 128, (B_ * N_) / 128), 256, GEMM_SMEM3_BYTES>>>(Wo, bo, out);
}

// round 17
// speedup vs baseline: 1.2428x; 1.0009x over previous
#include <cuda_runtime.h>
#include <cstdint>
#include <cstddef>

#define B_    2
#define N_    2048
#define DIM_  1024
#define H_    16
#define DH_   64
#define MM_   16
#define J_    2064          // N_ + MM_
#define KTOP_ 64
#define SCALE_ 0.125f

// ---------------- static device scratch ----------------
__device__ float g_q   [(size_t)B_*H_*N_*DH_];      // (b,h,i,d)
__device__ float g_k   [(size_t)B_*H_*J_*DH_];      // (b,h,j,d), j<M = mem
__device__ float g_v   [(size_t)B_*H_*J_*DH_];
__device__ float g_smix[(size_t)B_*H_*N_*J_];       // mixed scores (b,k,i,j)
__device__ float g_att [(size_t)B_*N_*DIM_];        // attention output (b,i,k*64+d)

// ---------------- tf32 MMA helpers -----------------------------------------------
__device__ __forceinline__ unsigned to_tf32(float x)
{
    unsigned r;
    asm("cvt.rna.tf32.f32 %0, %1;" : "=r"(r) : "f"(x));
    return r;
}

__device__ __forceinline__ void mma_tf32(float& d0, float& d1, float& d2, float& d3,
                                         unsigned a0, unsigned a1, unsigned a2, unsigned a3,
                                         unsigned b0, unsigned b1)
{
    asm volatile("mma.sync.aligned.m16n8k8.row.col.f32.tf32.tf32.f32 "
                 "{%0,%1,%2,%3}, {%4,%5,%6,%7}, {%8,%9}, {%0,%1,%2,%3};\n"
                 : "+f"(d0), "+f"(d1), "+f"(d2), "+f"(d3)
                 : "r"(a0), "r"(a1), "r"(a2), "r"(a3), "r"(b0), "r"(b1));
}

__device__ __forceinline__ unsigned smem_u32(const void* p)
{
    return (unsigned)__cvta_generic_to_shared(p);
}
#define CP16(dst, src) asm volatile("cp.async.cg.shared.global [%0], [%1], 16;" :: "r"(dst), "l"(src))
#define CP_COMMIT()    asm volatile("cp.async.commit_group;")
#define CP_WAIT1()     asm volatile("cp.async.wait_group 1;")

// ======= 128x128 / BK=16 tf32x3 GEMM, 3-stage cp.async, ONE barrier per slab =====
struct GemmSmem3 {
    float As[3][128][20];   // [stage][m][k]  banks: 20*grp+tig -> conflict-free
    float Bs[3][16][136];   // [stage][k][n]  banks: 8*tig+grp  -> conflict-free
};
#define GEMM_SMEM3_BYTES ((int)sizeof(GemmSmem3))   // 56832

__device__ __forceinline__ void gemm_tiles(GemmSmem3& S,
                                           const float* __restrict__ Aeff,
                                           const float* __restrict__ Bm,
                                           int Ndim, int Kdim,
                                           int m0, int n0,
                                           float acc[4][4][4])
{
    const int tid  = threadIdx.x;
    const int warp = tid >> 5;
    const int lane = tid & 31;
    const int wm   = warp & 1;
    const int wn   = warp >> 1;
    const int grp  = lane >> 2;
    const int tig  = lane & 3;

    const int arow  = tid >> 1;          // 0..127
    const int acol8 = (tid & 1) * 8;     // 0 or 8
    const int brow  = tid >> 4;          // 0..15
    const int bcol8 = (tid & 15) * 8;    // 0..120

    const float* ag = Aeff + (size_t)(m0 + arow) * Kdim + acol8;
    const float* bg = Bm + n0 + bcol8;

    unsigned a_dst[3], b_dst[3];
#pragma unroll
    for (int st = 0; st < 3; st++) {
        a_dst[st] = smem_u32(&S.As[st][arow][acol8]);
        b_dst[st] = smem_u32(&S.Bs[st][brow][bcol8]);
    }

    const int nslabs = Kdim >> 4;        // >= 2 always here

    // prologue: stages 0 and 1 (two committed groups)
#pragma unroll
    for (int st = 0; st < 2; st++) {
        const int k0 = st * 16;
        CP16(a_dst[st],      ag + k0);
        CP16(a_dst[st] + 16, ag + k0 + 4);
        CP16(b_dst[st],      bg + (size_t)(k0 + brow) * Ndim);
        CP16(b_dst[st] + 16, bg + (size_t)(k0 + brow) * Ndim + 4);
        CP_COMMIT();
    }

    int s = 0;
    for (int t = 0; t < nslabs; t++) {
        CP_WAIT1();             // slab t's group retired (own thread's)
        __syncthreads();        // ...and visible to all; also closes stage reuse

        // MMA phase on stage s = t%3
#pragma unroll
        for (int ks = 0; ks < 2; ks++) {
            const int kk = ks * 8 + tig;
            unsigned ah[4][4], al[4][4], bh[4][2], bl[4][2];
#pragma unroll
            for (int nf = 0; nf < 4; nf++) {
                const int col = wn * 32 + nf * 8 + grp;
                const float b0f = S.Bs[s][kk][col];
                const float b1f = S.Bs[s][kk + 4][col];
                bh[nf][0] = to_tf32(b0f);
                bh[nf][1] = to_tf32(b1f);
                bl[nf][0] = to_tf32(b0f - __uint_as_float(bh[nf][0]));
                bl[nf][1] = to_tf32(b1f - __uint_as_float(bh[nf][1]));
            }
#pragma unroll
            for (int mf = 0; mf < 4; mf++) {
                const int row = wm * 64 + mf * 16 + grp;
                const float a0f = S.As[s][row][kk];
                const float a1f = S.As[s][row + 8][kk];
                const float a2f = S.As[s][row][kk + 4];
                const float a3f = S.As[s][row + 8][kk + 4];
                ah[mf][0] = to_tf32(a0f); ah[mf][1] = to_tf32(a1f);
                ah[mf][2] = to_tf32(a2f); ah[mf][3] = to_tf32(a3f);
                al[mf][0] = to_tf32(a0f - __uint_as_float(ah[mf][0]));
                al[mf][1] = to_tf32(a1f - __uint_as_float(ah[mf][1]));
                al[mf][2] = to_tf32(a2f - __uint_as_float(ah[mf][2]));
                al[mf][3] = to_tf32(a3f - __uint_as_float(ah[mf][3]));
            }
#pragma unroll
            for (int mf = 0; mf < 4; mf++)
#pragma unroll
                for (int nf = 0; nf < 4; nf++) {
                    float* d = acc[mf][nf];
                    mma_tf32(d[0], d[1], d[2], d[3],
                             ah[mf][0], ah[mf][1], ah[mf][2], ah[mf][3],
                             bh[nf][0], bh[nf][1]);
                    mma_tf32(d[0], d[1], d[2], d[3],
                             al[mf][0], al[mf][1], al[mf][2], al[mf][3],
                             bh[nf][0], bh[nf][1]);
                    mma_tf32(d[0], d[1], d[2], d[3],
                             ah[mf][0], ah[mf][1], ah[mf][2], ah[mf][3],
                             bl[nf][0], bl[nf][1]);
                }
        }

        // issue next-next slab's loads AFTER the MMA phase: target stage
        // (t+2)%3 == (t-1)%3, whose readers all passed this iteration's barrier.
        if (t + 2 < nslabs) {
            const int ns = (s + 2 >= 3) ? s - 1 : s + 2;   // (t+2)%3
            const int k0 = (t + 2) << 4;
            CP16(a_dst[ns],      ag + k0);
            CP16(a_dst[ns] + 16, ag + k0 + 4);
            CP16(b_dst[ns],      bg + (size_t)(k0 + brow) * Ndim);
            CP16(b_dst[ns] + 16, bg + (size_t)(k0 + brow) * Ndim + 4);
        }
        CP_COMMIT();            // possibly-empty group keeps the count uniform
        s = (s + 1 >= 3) ? 0 : s + 1;
    }
}

// ---- merged Q/KV projection + mem_k/mem_v fill ----------------------------------
// grid = (25, 32): tiles x=0..23 = [Wq | Wkv] columns; x=24 = mem fill
// (32 CTAs x 1024 elems = 32768 = B*H*M*DH).
__global__ void __launch_bounds__(256) k_gemm_qkv(const float* __restrict__ x,
                                                  const float* __restrict__ Wq,
                                                  const float* __restrict__ Wkv,
                                                  const float* __restrict__ mk,
                                                  const float* __restrict__ mv)
{
    extern __shared__ char smem_raw[];
    GemmSmem3& S = *reinterpret_cast<GemmSmem3*>(smem_raw);

    if (blockIdx.x == 24) {
        const int slice = blockIdx.y;
        for (int t = threadIdx.x; t < 1024; t += 256) {
            const int idx = slice * 1024 + t;       // < 32768 = B_*H_*MM_*DH_
            const int d = idx & 63;
            int r = idx >> 6;
            const int j = r % MM_;  r /= MM_;
            const int h = r % H_;
            const int b = r / H_;
            const size_t dst = (((size_t)(b * H_ + h)) * J_ + j) * DH_ + d;
            const size_t src = ((size_t)h * MM_ + j) * DH_ + d;
            g_k[dst] = mk[src];
            g_v[dst] = mv[src];
        }
        return;
    }

    const int n0g = blockIdx.x * 128;
    const int m0  = blockIdx.y * 128;
    const bool isQ = n0g < DIM_;
    const float* Bm = isQ ? Wq : Wkv;
    const int Ndim  = isQ ? DIM_ : 2 * DIM_;
    const int n0    = isQ ? n0g : n0g - DIM_;

    float acc[4][4][4];
#pragma unroll
    for (int mf = 0; mf < 4; mf++)
#pragma unroll
        for (int nf = 0; nf < 4; nf++)
#pragma unroll
            for (int e = 0; e < 4; e++) acc[mf][nf][e] = 0.f;

    gemm_tiles(S, x, Bm, Ndim, DIM_, m0, n0, acc);

    const int tid  = threadIdx.x;
    const int warp = tid >> 5;
    const int lane = tid & 31;
    const int wm   = warp & 1;
    const int wn   = warp >> 1;
    const int grp  = lane >> 2;
    const int tig  = lane & 3;

#pragma unroll
    for (int mf = 0; mf < 4; mf++) {
        const int r0 = m0 + wm * 64 + mf * 16 + grp;
#pragma unroll
        for (int nf = 0; nf < 4; nf++) {
            const int c0 = n0 + wn * 32 + nf * 8 + tig * 2;
            const float* d = acc[mf][nf];
#pragma unroll
            for (int half = 0; half < 2; half++) {
                const int m = r0 + half * 8;
                const float2 o = make_float2(d[half * 2], d[half * 2 + 1]);
                const int b = m >> 11;
                const int i = m & (N_ - 1);
                if (isQ) {
                    const int h = c0 >> 6, dd = c0 & 63;
                    *(float2*)(g_q + (((size_t)(b * H_ + h)) * N_ + i) * DH_ + dd) = o;
                } else if (c0 < DIM_) {
                    const int h = c0 >> 6, dd = c0 & 63;
                    *(float2*)(g_k + (((size_t)(b * H_ + h)) * J_ + MM_ + i) * DH_ + dd) = o;
                } else {
                    const int c = c0 - DIM_;
                    const int h = c >> 6, dd = c & 63;
                    *(float2*)(g_v + (((size_t)(b * H_ + h)) * J_ + MM_ + i) * DH_ + dd) = o;
                }
            }
        }
    }
}

// ---- output projection: C = g_att @ Wo + bo -------------------------------------
__global__ void __launch_bounds__(256) k_gemm_o(const float* __restrict__ Wo,
                                                const float* __restrict__ bias,
                                                float* __restrict__ C)
{
    extern __shared__ char smem_raw[];
    GemmSmem3& S = *reinterpret_cast<GemmSmem3*>(smem_raw);

    const int m0 = blockIdx.y * 128;
    const int n0 = blockIdx.x * 128;

    float acc[4][4][4];
#pragma unroll
    for (int mf = 0; mf < 4; mf++)
#pragma unroll
        for (int nf = 0; nf < 4; nf++)
#pragma unroll
            for (int e = 0; e < 4; e++) acc[mf][nf][e] = 0.f;

    gemm_tiles(S, g_att, Wo, DIM_, DIM_, m0, n0, acc);

    const int tid  = threadIdx.x;
    const int warp = tid >> 5;
    const int lane = tid & 31;
    const int wm   = warp & 1;
    const int wn   = warp >> 1;
    const int grp  = lane >> 2;
    const int tig  = lane & 3;

#pragma unroll
    for (int mf = 0; mf < 4; mf++) {
        const int r0 = m0 + wm * 64 + mf * 16 + grp;
#pragma unroll
        for (int nf = 0; nf < 4; nf++) {
            const int c0 = n0 + wn * 32 + nf * 8 + tig * 2;
            const float* d = acc[mf][nf];
#pragma unroll
            for (int half = 0; half < 2; half++) {
                const int m = r0 + half * 8;
                float2 o = make_float2(d[half * 2], d[half * 2 + 1]);
                o.x += bias[c0]; o.y += bias[c0 + 1];
                *(float2*)(C + (size_t)m * DIM_ + c0) = o;
            }
        }
    }
}

// ---------------- fused QK^T + head-mix via tf32x3 MMA, double-buffered ----------
__global__ void __launch_bounds__(256, 2) k_dots_mix(const float* __restrict__ pre)
{
    const int b  = blockIdx.z;
    const int i0 = blockIdx.y * 32;
    const int j0 = blockIdx.x * 32;
    if (j0 > i0 + 31 + MM_) return;     // fully above causal band

    __shared__ __align__(16) float Qs[2][32][68];
    __shared__ __align__(16) float Ks[2][32][68];
    __shared__ __align__(16) float Ppre[H_ * H_];

    const int tid  = threadIdx.x;
    const int warp = tid >> 5;
    const int lane = tid & 31;
    const int wi   = warp & 1;
    const int wj   = warp >> 1;
    const int grp  = lane >> 2;
    const int tig  = lane & 3;

    Ppre[tid] = pre[tid] * SCALE_;      // fold softmax scale into the mix matrix

    const int lr = tid >> 3;
    const int lc = (tid & 7) << 2;
    const int jrow = j0 + lr;
    const bool jvalid = jrow < J_;

    const int ri = wi * 16 + grp;
    const int rj = wj * 8 + grp;

    float acc[H_][4];
#pragma unroll
    for (int ko = 0; ko < H_; ko++)
#pragma unroll
        for (int e = 0; e < 4; e++) acc[ko][e] = 0.f;

    const float* qbase = g_q + ((size_t)b * H_ * N_ + (size_t)(i0 + lr)) * DH_;
    const float* kbase = g_k + ((size_t)b * H_ * J_ + (size_t)jrow) * DH_;
    const size_t qstep = (size_t)N_ * DH_;      // per-head stride
    const size_t kstep = (size_t)J_ * DH_;

    float4 q0r = *(const float4*)(qbase + lc);
    float4 q1r = *(const float4*)(qbase + lc + 32);
    float4 k0r, k1r;
    if (jvalid) {
        k0r = *(const float4*)(kbase + lc);
        k1r = *(const float4*)(kbase + lc + 32);
    } else {
        k0r = make_float4(0.f, 0.f, 0.f, 0.f);
        k1r = k0r;
    }
    *(float4*)&Qs[0][lr][lc]      = q0r;
    *(float4*)&Qs[0][lr][lc + 32] = q1r;
    *(float4*)&Ks[0][lr][lc]      = k0r;
    *(float4*)&Ks[0][lr][lc + 32] = k1r;

#pragma unroll 1
    for (int h = 0; h < H_; h++) {
        const int cb = h & 1;
        if (h + 1 < H_) {
            const float* qn = qbase + (size_t)(h + 1) * qstep;
            q0r = *(const float4*)(qn + lc);
            q1r = *(const float4*)(qn + lc + 32);
            if (jvalid) {
                const float* kn = kbase + (size_t)(h + 1) * kstep;
                k0r = *(const float4*)(kn + lc);
                k1r = *(const float4*)(kn + lc + 32);
            }
        }
        __syncthreads();

        float s0 = 0.f, s1 = 0.f, s2 = 0.f, s3 = 0.f;
#pragma unroll
        for (int k0 = 0; k0 < DH_; k0 += 8) {
            const float a0f = Qs[cb][ri]    [k0 + tig];
            const float a1f = Qs[cb][ri + 8][k0 + tig];
            const float a2f = Qs[cb][ri]    [k0 + tig + 4];
            const float a3f = Qs[cb][ri + 8][k0 + tig + 4];
            const float b0f = Ks[cb][rj][k0 + tig];
            const float b1f = Ks[cb][rj][k0 + tig + 4];

            const unsigned a0h = to_tf32(a0f), a1h = to_tf32(a1f);
            const unsigned a2h = to_tf32(a2f), a3h = to_tf32(a3f);
            const unsigned b0h = to_tf32(b0f), b1h = to_tf32(b1f);
            const unsigned a0l = to_tf32(a0f - __uint_as_float(a0h));
            const unsigned a1l = to_tf32(a1f - __uint_as_float(a1h));
            const unsigned a2l = to_tf32(a2f - __uint_as_float(a2h));
            const unsigned a3l = to_tf32(a3f - __uint_as_float(a3h));
            const unsigned b0l = to_tf32(b0f - __uint_as_float(b0h));
            const unsigned b1l = to_tf32(b1f - __uint_as_float(b1h));

            mma_tf32(s0, s1, s2, s3, a0h, a1h, a2h, a3h, b0h, b1h);   // hi*hi
            mma_tf32(s0, s1, s2, s3, a0l, a1l, a2l, a3l, b0h, b1h);   // lo*hi
            mma_tf32(s0, s1, s2, s3, a0h, a1h, a2h, a3h, b0l, b1l);   // hi*lo
        }

        // mixing: 4x LDS.128 per head over the pre-scaled mix row
        const float4* prow = (const float4*)&Ppre[h * H_];
#pragma unroll
        for (int kq = 0; kq < 4; kq++) {
            const float4 p = prow[kq];
            acc[kq * 4 + 0][0] += p.x * s0; acc[kq * 4 + 0][1] += p.x * s1;
            acc[kq * 4 + 0][2] += p.x * s2; acc[kq * 4 + 0][3] += p.x * s3;
            acc[kq * 4 + 1][0] += p.y * s0; acc[kq * 4 + 1][1] += p.y * s1;
            acc[kq * 4 + 1][2] += p.y * s2; acc[kq * 4 + 1][3] += p.y * s3;
            acc[kq * 4 + 2][0] += p.z * s0; acc[kq * 4 + 2][1] += p.z * s1;
            acc[kq * 4 + 2][2] += p.z * s2; acc[kq * 4 + 2][3] += p.z * s3;
            acc[kq * 4 + 3][0] += p.w * s0; acc[kq * 4 + 3][1] += p.w * s1;
            acc[kq * 4 + 3][2] += p.w * s2; acc[kq * 4 + 3][3] += p.w * s3;
        }

        if (h + 1 < H_) {
            const int nb = cb ^ 1;
            *(float4*)&Qs[nb][lr][lc]      = q0r;
            *(float4*)&Qs[nb][lr][lc + 32] = q1r;
            *(float4*)&Ks[nb][lr][lc]      = k0r;
            *(float4*)&Ks[nb][lr][lc + 32] = k1r;
        }
    }

    const int gi = i0 + ri;
    const int gj = j0 + wj * 8 + tig * 2;
#pragma unroll
    for (int ko = 0; ko < H_; ko++) {
        const size_t base = (((size_t)(b * H_ + ko)) * N_ + gi) * J_ + gj;
        if (gj < J_) {
            g_smix[base]              = acc[ko][0];
            g_smix[base + 8 * J_]     = acc[ko][2];
        }
        if (gj + 1 < J_) {
            g_smix[base + 1]          = acc[ko][1];
            g_smix[base + 8 * J_ + 1] = acc[ko][3];
        }
    }
}

// ---------------- per-row top-k + softmax + sparse A*V (vectorized sweeps) -------
__device__ __forceinline__ unsigned fkey(float f)
{
    unsigned u = __float_as_uint(f);
    return (u & 0x80000000u) ? ~u : (u | 0x80000000u);
}
__device__ __forceinline__ float finv(unsigned k)
{
    return (k & 0x80000000u) ? __uint_as_float(k ^ 0x80000000u)
                             : __uint_as_float(~k);
}

// single-warp suffix-scan over 256 bins; finds bin B with suffix(B) >= kth > suffix(B+1)
__device__ __forceinline__ void scan_bins(const int* hist, int kth, int tid,
                                          int* s_bin, int* s_above)
{
    if (tid < 32) {
        int loc[8];
        int sum = 0;
#pragma unroll
        for (int e = 0; e < 8; e++) { loc[e] = hist[tid * 8 + e]; sum += loc[e]; }
        int v = sum;
#pragma unroll
        for (int o = 1; o < 32; o <<= 1) {
            const int u = __shfl_down_sync(0xffffffffu, v, o);
            if (tid + o < 32) v += u;
        }
        const int after_lane = v - sum;        // count in lanes > tid
        int run = after_lane;
        int sfx[8];
#pragma unroll
        for (int e = 7; e >= 0; e--) { run += loc[e]; sfx[e] = run; }
#pragma unroll
        for (int e = 0; e < 8; e++) {
            const int above = (e == 7) ? after_lane : sfx[e + 1];
            if (sfx[e] >= kth && above < kth) { *s_bin = tid * 8 + e; *s_above = above; }
        }
    }
}

__global__ void __launch_bounds__(256) k_topk_av()
{
    const int i  = blockIdx.x;
    const int ko = blockIdx.y;
    const int b  = blockIdx.z;
    const int tid = threadIdx.x;
    const int lane = tid & 31;
    const int jmax = min(J_, i + MM_ + 1);

    __shared__ __align__(16) unsigned skeys[J_];
    __shared__ int   sidx[J_];       // survivor indices; reused as candB
    __shared__ float swgt[J_];       // survivor weights; reused as candA
    __shared__ int   hist[256];
    __shared__ unsigned redk[8];
    __shared__ float redf[8];
    __shared__ unsigned s_maxk, s_tkey;
    __shared__ float s_sum;
    __shared__ int   s_bin, s_above, s_cnt;
    __shared__ float accb[4][64];

    const float* row = g_smix + (((size_t)(b * H_ + ko)) * N_ + i) * J_;

    // --- sweep 1 (vectorized x4): load keys + top-byte histogram ----------------
    hist[tid] = 0;
    __syncthreads();
    unsigned lmax = 0u;
    const int nIterV = (jmax + 1023) >> 10;         // uniform across block
    for (int it = 0; it < nIterV; it++) {
        const int base = (tid << 2) + (it << 10);   // multiple of 4, < J_ when any valid
        unsigned k4[4];
        if (base < jmax) {                           // safe: row has J_ elems, J_%4==0
            const float4 v4 = *(const float4*)(row + base);
            k4[0] = fkey(v4.x); k4[1] = fkey(v4.y);
            k4[2] = fkey(v4.z); k4[3] = fkey(v4.w);
            *(uint4*)&skeys[base] = make_uint4(k4[0], k4[1], k4[2], k4[3]);
        } else {
            k4[0] = k4[1] = k4[2] = k4[3] = 0u;
        }
#pragma unroll
        for (int e = 0; e < 4; e++) {
            const bool valid = (base + e) < jmax;
            if (valid) lmax = max(lmax, k4[e]);
            const unsigned bin = valid ? (k4[e] >> 24) : 300u;
            const unsigned mmask = __match_any_sync(0xffffffffu, bin);
            if (valid && (mmask & ((1u << lane) - 1u)) == 0u)
                atomicAdd(&hist[bin], __popc(mmask));
        }
    }
#pragma unroll
    for (int o = 16; o > 0; o >>= 1) lmax = max(lmax, __shfl_xor_sync(0xffffffffu, lmax, o));
    if (lane == 0) redk[tid >> 5] = lmax;
    __syncthreads();
    if (tid == 0) {
        unsigned m = redk[0];
#pragma unroll
        for (int w = 1; w < 8; w++) m = max(m, redk[w]);
        s_maxk = m;
    }
    __syncthreads();
    const float vmax = finv(s_maxk);

    // --- exact K-th largest key: bin scan + boundary-bin candidate select -------
    unsigned tkey = 0u;
    if (jmax > KTOP_) {
        scan_bins(hist, KTOP_, tid, &s_bin, &s_above);
        __syncthreads();
        const int b0 = s_bin;
        int kth = KTOP_ - s_above;

        if (tid == 0) s_cnt = 0;
        __syncthreads();
        unsigned* candA = (unsigned*)swgt;
        unsigned* candB = (unsigned*)sidx;
        // sweep 2 (vectorized x4): scatter boundary-bin candidates
        for (int it = 0; it < nIterV; it++) {
            const int base = (tid << 2) + (it << 10);
            if (base < jmax) {
                const uint4 k4 = *(const uint4*)&skeys[base];
                const unsigned ks[4] = {k4.x, k4.y, k4.z, k4.w};
#pragma unroll
                for (int e = 0; e < 4; e++)
                    if ((base + e) < jmax && (ks[e] >> 24) == (unsigned)b0)
                        candA[atomicAdd(&s_cnt, 1)] = ks[e];
            }
        }
        __syncthreads();
        int c = s_cnt;
        unsigned* cur = candA;
        unsigned* alt = candB;
        int shift = 16;
        while (c > 48 && shift >= 0) {
            hist[tid] = 0;
            __syncthreads();
            for (int t = tid; t < c; t += 256)
                atomicAdd(&hist[(cur[t] >> shift) & 255u], 1);
            __syncthreads();
            scan_bins(hist, kth, tid, &s_bin, &s_above);
            __syncthreads();
            const int bsel = s_bin;
            kth -= s_above;
            if (tid == 0) s_cnt = 0;
            __syncthreads();
            for (int t = tid; t < c; t += 256)
                if (((cur[t] >> shift) & 255u) == (unsigned)bsel)
                    alt[atomicAdd(&s_cnt, 1)] = cur[t];
            __syncthreads();
            c = s_cnt;
            unsigned* tmp = cur; cur = alt; alt = tmp;
            shift -= 8;
        }
        if (shift < 0) {
            if (tid == 0) s_tkey = cur[0];          // all remaining keys identical
        } else {
            // exact rank-count select among c (<=48) candidates
            for (int t = tid; t < c; t += 256) {
                const unsigned x = cur[t];
                int gt = 0, ge = 0;
                for (int u = 0; u < c; u++) { gt += (cur[u] > x); ge += (cur[u] >= x); }
                if (gt < kth && ge >= kth) s_tkey = x;
            }
        }
        __syncthreads();
        tkey = s_tkey;
    }

    // --- sweep 3 (vectorized x4): compact survivors + exp-sum -------------------
    if (tid == 0) s_cnt = 0;
    __syncthreads();
    float lsum = 0.f;
    for (int it = 0; it < nIterV; it++) {
        const int base = (tid << 2) + (it << 10);
        if (base < jmax) {
            const uint4 k4 = *(const uint4*)&skeys[base];
            const unsigned ks[4] = {k4.x, k4.y, k4.z, k4.w};
#pragma unroll
            for (int e = 0; e < 4; e++) {
                if ((base + e) < jmax && ks[e] >= tkey) {
                    const float w = __expf(finv(ks[e]) - vmax);
                    lsum += w;
                    const int p = atomicAdd(&s_cnt, 1);
                    sidx[p] = base + e;
                    swgt[p] = w;
                }
            }
        }
    }
#pragma unroll
    for (int o = 16; o > 0; o >>= 1) lsum += __shfl_xor_sync(0xffffffffu, lsum, o);
    if (lane == 0) redf[tid >> 5] = lsum;
    __syncthreads();
    if (tid == 0) {
        float t = 0.f;
#pragma unroll
        for (int w = 0; w < 8; w++) t += redf[w];
        s_sum = t;
    }
    __syncthreads();
    const float sumexp = s_sum;
    const int nsurv = s_cnt;

    // --- gather-weighted sum over surviving v rows ------------------------------
    const int d = tid & 63;
    const int g = tid >> 6;
    float acc = 0.f;
    const float* vb = g_v + ((size_t)(b * H_ + ko)) * J_ * DH_ + d;
    for (int s = g; s < nsurv; s += 4)
        acc += swgt[s] * vb[(size_t)sidx[s] * DH_];
    accb[g][d] = acc;
    __syncthreads();
    if (g == 0) {
        const float tot = accb[0][d] + accb[1][d] + accb[2][d] + accb[3][d];
        g_att[((size_t)(b * N_ + i)) * DIM_ + ko * DH_ + d] = tot / sumexp;
    }
}

// ---------------- launch ---------------------------------------------------------
extern "C" void kernel_launch(void* const* d_in, const int* in_sizes, int n_in,
                              void* d_out, int out_size)
{
    (void)in_sizes; (void)n_in; (void)out_size;
    const float* x    = (const float*)d_in[0];
    const float* Wq   = (const float*)d_in[1];
    const float* Wkv  = (const float*)d_in[2];
    const float* Wo   = (const float*)d_in[3];
    const float* bo   = (const float*)d_in[4];
    const float* pre  = (const float*)d_in[5];
    const float* memk = (const float*)d_in[7];
    const float* memv = (const float*)d_in[8];
    float* out = (float*)d_out;

    cudaFuncSetAttribute(k_gemm_qkv, cudaFuncAttributeMaxDynamicSharedMemorySize, GEMM_SMEM3_BYTES);
    cudaFuncSetAttribute(k_gemm_o,   cudaFuncAttributeMaxDynamicSharedMemorySize, GEMM_SMEM3_BYTES);

    k_gemm_qkv<<<dim3(25, (B_ * N_) / 128), 256, GEMM_SMEM3_BYTES>>>(x, Wq, Wkv, memk, memv);
    k_dots_mix<<<dim3((J_ + 31) / 32, N_ / 32, B_), 256>>>(pre);
    k_topk_av<<<dim3(N_, H_, B_), 256>>>();
    k_gemm_o<<<dim3(DIM_ / 128, (B_ * N_) / 128), 256, GEMM_SMEM3_BYTES>>>(Wo, bo, out);
}